// round 5
// baseline (speedup 1.0000x reference)
#include <cuda_runtime.h>
#include <math.h>

#define BB 8
#define NN 2048
#define CC 768
#define HH 12
#define MM 1536
#define RR 512
#define NSRC 1024
#define NDST 1024
#define C3 2304

__device__ __forceinline__ float tf32r(float x) {
    unsigned r; asm("cvt.rna.tf32.f32 %0, %1;" : "=r"(r) : "f"(x));
    return __uint_as_float(r);
}
__device__ __forceinline__ void mma8(float c[4], const unsigned a[4], const unsigned b[2]) {
    asm volatile("mma.sync.aligned.m16n8k8.row.col.f32.tf32.tf32.f32 "
        "{%0,%1,%2,%3}, {%4,%5,%6,%7}, {%8,%9}, {%0,%1,%2,%3};"
        : "+f"(c[0]), "+f"(c[1]), "+f"(c[2]), "+f"(c[3])
        : "r"(a[0]), "r"(a[1]), "r"(a[2]), "r"(a[3]), "r"(b[0]), "r"(b[1]));
}
#define U(x) __float_as_uint(x)

// ---------------- scratch ----------------
__device__ float g_metric[(size_t)BB * NN * CC];
__device__ float g_pmax[BB * 8 * NSRC];
__device__ int   g_pidx[BB * 8 * NSRC];
__device__ float g_nodemax[BB * NSRC];
__device__ int   g_nodeidx[BB * NSRC];
__device__ int   g_srcidx[BB * RR];
__device__ int   g_dstidx[BB * RR];
__device__ int   g_unmidx[BB * RR];
__device__ int   g_gather[BB * NSRC];
__device__ float g_counts[BB * NDST];
__device__ float g_xm[(size_t)BB * MM * CC];
__device__ float g_qkv[(size_t)BB * MM * C3];
__device__ float g_attn[(size_t)BB * MM * CC];
__device__ float g_y[(size_t)BB * MM * CC];

// ---------------- 1. normalized metric (exact fp32, single pass) ----------------
__global__ void metric_k(const float* __restrict__ x) {
    int row = blockIdx.x;
    int tid = threadIdx.x;                 // 256
    const float* p = x + (size_t)row * CC;
    float* q = g_metric + (size_t)row * CC;
    float v0 = p[tid], v1 = p[tid + 256], v2 = p[tid + 512];
    float s = v0 * v0 + v1 * v1 + v2 * v2;
    __shared__ float red[256];
    red[tid] = s; __syncthreads();
    for (int o = 128; o > 0; o >>= 1) {
        if (tid < o) red[tid] += red[tid + o];
        __syncthreads();
    }
    float nrm = sqrtf(red[0]);
    q[tid] = v0 / nrm; q[tid + 256] = v1 / nrm; q[tid + 512] = v2 / nrm;
}

// ---------------- 2a. matching scores, fp32-exact (verified in R3/R4) ----------------
__global__ __launch_bounds__(256, 2) void match128_k() {
    __shared__ float As[8][132];
    __shared__ float Bs[8][132];
    int dt = blockIdx.x, st = blockIdx.y, b = blockIdx.z;
    const float* mb = g_metric + (size_t)b * NN * CC;
    int tid = threadIdx.x;
    int tx = tid & 15, ty = tid >> 4;
    int lm = tid & 127, kq = (tid >> 7) * 4;
    const float* arow = mb + (size_t)(2 * (st * 128 + lm)) * CC + kq;
    const float* brow = mb + (size_t)(2 * (dt * 128 + lm) + 1) * CC + kq;
    float acc[8][8] = {};

    for (int k0 = 0; k0 < CC; k0 += 8) {
        float4 av = *(const float4*)(arow + k0);
        float4 bv = *(const float4*)(brow + k0);
        As[kq + 0][lm] = av.x; As[kq + 1][lm] = av.y;
        As[kq + 2][lm] = av.z; As[kq + 3][lm] = av.w;
        Bs[kq + 0][lm] = bv.x; Bs[kq + 1][lm] = bv.y;
        Bs[kq + 2][lm] = bv.z; Bs[kq + 3][lm] = bv.w;
        __syncthreads();
#pragma unroll
        for (int kk = 0; kk < 8; kk++) {
            float4 a0 = *(const float4*)&As[kk][ty * 8];
            float4 a1 = *(const float4*)&As[kk][ty * 8 + 4];
            float4 b0 = *(const float4*)&Bs[kk][tx * 8];
            float4 b1 = *(const float4*)&Bs[kk][tx * 8 + 4];
            float am[8] = {a0.x, a0.y, a0.z, a0.w, a1.x, a1.y, a1.z, a1.w};
            float bm[8] = {b0.x, b0.y, b0.z, b0.w, b1.x, b1.y, b1.z, b1.w};
#pragma unroll
            for (int i = 0; i < 8; i++)
#pragma unroll
                for (int j = 0; j < 8; j++)
                    acc[i][j] += am[i] * bm[j];
        }
        __syncthreads();
    }
#pragma unroll
    for (int i = 0; i < 8; i++) {
        float bv = acc[i][0]; int bj = 0;
#pragma unroll
        for (int j = 1; j < 8; j++)
            if (acc[i][j] > bv) { bv = acc[i][j]; bj = j; }
        int bi = dt * 128 + tx * 8 + bj;
        for (int off = 8; off; off >>= 1) {
            float ov = __shfl_xor_sync(0xffffffffu, bv, off);
            int   oi = __shfl_xor_sync(0xffffffffu, bi, off);
            if (ov > bv || (ov == bv && oi < bi)) { bv = ov; bi = oi; }
        }
        if (tx == 0) {
            int r = st * 128 + ty * 8 + i;
            g_pmax[(b * 8 + dt) * NSRC + r] = bv;
            g_pidx[(b * 8 + dt) * NSRC + r] = bi;
        }
    }
}

__global__ void matchred_k() {
    int g = blockIdx.x * 256 + threadIdx.x;
    int b = g >> 10, r = g & 1023;
    float bv = g_pmax[(b * 8) * NSRC + r];
    int   bi = g_pidx[(b * 8) * NSRC + r];
    for (int dt = 1; dt < 8; dt++) {
        float v = g_pmax[(b * 8 + dt) * NSRC + r];
        if (v > bv) { bv = v; bi = g_pidx[(b * 8 + dt) * NSRC + r]; }
    }
    g_nodemax[b * NSRC + r] = bv;
    g_nodeidx[b * NSRC + r] = bi;
}

// ---------------- 3. top-k: 1024 threads, parallel rank scan ----------------
__global__ void topk_k() {
    __shared__ unsigned long long key[1024];
    __shared__ int cnt[1024];
    __shared__ int mrg[1024];
    __shared__ int scn[1024];
    int b = blockIdx.x, tid = threadIdx.x;   // 1024

    {
        float v = g_nodemax[b * NSRC + tid];
        unsigned u = __float_as_uint(v);
        u = (u & 0x80000000u) ? ~u : (u | 0x80000000u);
        key[tid] = ((unsigned long long)(~u) << 32) | (unsigned)tid;
        cnt[tid] = 1; mrg[tid] = 0;
    }
    __syncthreads();
    for (int k = 2; k <= 1024; k <<= 1)
        for (int j = k >> 1; j > 0; j >>= 1) {
            int p = tid ^ j;
            if (p > tid) {
                bool up = ((tid & k) == 0);
                unsigned long long a = key[tid], c2 = key[p];
                if ((a > c2) == up) { key[tid] = c2; key[p] = a; }
            }
            __syncthreads();
        }
    if (tid < 512) {
        int s = (int)(key[tid] & 0xffffffffu);
        int d = g_nodeidx[b * NSRC + s];
        g_srcidx[b * RR + tid] = s;
        g_dstidx[b * RR + tid] = d;
        mrg[s] = 1;
        atomicAdd(&cnt[d], 1);
    }
    __syncthreads();
    int um = mrg[tid] ? 0 : 1;
    scn[tid] = um; __syncthreads();
    for (int off = 1; off < 1024; off <<= 1) {
        int v = scn[tid];
        int v2 = (tid >= off) ? scn[tid - off] : 0;
        __syncthreads();
        scn[tid] = v + v2; __syncthreads();
    }
    int rnk = scn[tid] - um;
    if (um) { g_unmidx[b * RR + rnk] = tid; g_gather[b * NSRC + tid] = NDST + rnk; }
    else    { g_gather[b * NSRC + tid] = g_nodeidx[b * NSRC + tid]; }
    g_counts[b * NDST + tid] = (float)cnt[tid];
}

// ---------------- 4-6. merge build (unchanged, verified) ----------------
__global__ void build_xm_k(const float* __restrict__ x) {
    int row = blockIdx.x;
    int b = row / MM, j = row - b * MM;
    const float* src;
    if (j < NDST) src = x + ((size_t)b * NN + 2 * j + 1) * CC;
    else { int s = g_unmidx[b * RR + (j - NDST)]; src = x + ((size_t)b * NN + 2 * s) * CC; }
    float* dst = g_xm + (size_t)row * CC;
    int t = threadIdx.x;                    // 192
    *(float4*)&dst[t * 4] = *(const float4*)&src[t * 4];
}

__global__ void merge_add_k(const float* __restrict__ x) {
    int b = blockIdx.x >> 9;
    int i = blockIdx.x & 511;
    int s = g_srcidx[b * RR + i];
    int d = g_dstidx[b * RR + i];
    const float* sp = x + ((size_t)b * NN + 2 * s) * CC;
    float* dp = g_xm + ((size_t)b * MM + d) * CC;
    int t = threadIdx.x;                    // 192
    float4 v = *(const float4*)&sp[t * 4];
    atomicAdd(&dp[t * 4 + 0], v.x);
    atomicAdd(&dp[t * 4 + 1], v.y);
    atomicAdd(&dp[t * 4 + 2], v.z);
    atomicAdd(&dp[t * 4 + 3], v.w);
}

__global__ void divide_k() {
    int b = blockIdx.x >> 10;
    int d = blockIdx.x & 1023;
    float inv = 1.0f / g_counts[b * NDST + d];
    float* dp = g_xm + ((size_t)b * MM + d) * CC;
    int t = threadIdx.x;                    // 192
    float4 v = *(float4*)&dp[t * 4];
    v.x *= inv; v.y *= inv; v.z *= inv; v.w *= inv;
    *(float4*)&dp[t * 4] = v;
}

// ---------------- 7. tf32 GEMM, k-interleaved smem, double-buffered ----------------
// phys k layout per 16-chunk: phys = 4*(k&3) + (k>>2); row stride 20 words.
__global__ __launch_bounds__(256, 2) void gemm_tf32_k(
        const float* __restrict__ A, const float* __restrict__ Bm,
        const float* __restrict__ bias, float* __restrict__ Cm, int Nd) {
    __shared__ float As[2][128 * 20];
    __shared__ float Bs[2][128 * 20];
    int tid = threadIdx.x;
    int w = tid >> 5, l = tid & 31;
    int wm = w & 3, wn = w >> 2;
    int lr = l >> 2, lc = l & 3;
    int bm = blockIdx.y * 128, bn = blockIdx.x * 128;
    float acc[2][8][4] = {};

    // A loader: row ar, logical k quad aq (k = 16c + 4*aq + i)
    int ar = tid >> 2, aq = tid & 3;
    const float* Ap0 = A + (size_t)(bm + ar) * CC + 4 * aq;
    const float* Ap1 = Ap0 + (size_t)64 * CC;
    // B loader: col bn0 (+64), logical k quad bq
    int bq = tid & 3, bn0 = tid >> 2;
    const float* Bp = Bm + bn + bn0;

    float a0v[4], a1v[4], btv[2][4];
    {   // prefetch chunk 0
        float4 t0 = *(const float4*)Ap0;
        float4 t1 = *(const float4*)Ap1;
        a0v[0] = t0.x; a0v[1] = t0.y; a0v[2] = t0.z; a0v[3] = t0.w;
        a1v[0] = t1.x; a1v[1] = t1.y; a1v[2] = t1.z; a1v[3] = t1.w;
#pragma unroll
        for (int h = 0; h < 2; h++)
#pragma unroll
            for (int i = 0; i < 4; i++)
                btv[h][i] = Bp[(size_t)(4 * bq + i) * Nd + 64 * h];
    }
    {   // store chunk 0 -> buf 0
        float* Aw = As[0]; float* Bw = Bs[0];
#pragma unroll
        for (int i = 0; i < 4; i++) {
            Aw[ar * 20 + 4 * i + aq]        = tf32r(a0v[i]);
            Aw[(ar + 64) * 20 + 4 * i + aq] = tf32r(a1v[i]);
        }
#pragma unroll
        for (int h = 0; h < 2; h++)
#pragma unroll
            for (int i = 0; i < 4; i++)
                Bw[(bn0 + 64 * h) * 20 + 4 * i + bq] = tf32r(btv[h][i]);
    }
    __syncthreads();

    int buf = 0;
    for (int c = 0; c < 48; c++) {
        if (c < 47) {   // gmem prefetch next chunk
            int k0 = (c + 1) * 16;
            float4 t0 = *(const float4*)(Ap0 + k0);
            float4 t1 = *(const float4*)(Ap1 + k0);
            a0v[0] = t0.x; a0v[1] = t0.y; a0v[2] = t0.z; a0v[3] = t0.w;
            a1v[0] = t1.x; a1v[1] = t1.y; a1v[2] = t1.z; a1v[3] = t1.w;
#pragma unroll
            for (int h = 0; h < 2; h++)
#pragma unroll
                for (int i = 0; i < 4; i++)
                    btv[h][i] = Bp[(size_t)(k0 + 4 * bq + i) * Nd + 64 * h];
        }
        // compute on buf
        const float* Ar = As[buf];
        const float* Br = Bs[buf];
        unsigned af[2][2][4];
#pragma unroll
        for (int mt = 0; mt < 2; mt++) {
            float4 f0 = *(const float4*)&Ar[(wm * 32 + mt * 16 + lr) * 20 + 4 * lc];
            float4 f1 = *(const float4*)&Ar[(wm * 32 + mt * 16 + 8 + lr) * 20 + 4 * lc];
            af[mt][0][0] = U(f0.x); af[mt][0][1] = U(f1.x); af[mt][0][2] = U(f0.y); af[mt][0][3] = U(f1.y);
            af[mt][1][0] = U(f0.z); af[mt][1][1] = U(f1.z); af[mt][1][2] = U(f0.w); af[mt][1][3] = U(f1.w);
        }
#pragma unroll
        for (int nt = 0; nt < 8; nt++) {
            float4 fb = *(const float4*)&Br[(wn * 64 + nt * 8 + lr) * 20 + 4 * lc];
            unsigned b0[2] = {U(fb.x), U(fb.y)};
            unsigned b1[2] = {U(fb.z), U(fb.w)};
            mma8(acc[0][nt], af[0][0], b0);
            mma8(acc[1][nt], af[1][0], b0);
            mma8(acc[0][nt], af[0][1], b1);
            mma8(acc[1][nt], af[1][1], b1);
        }
        if (c < 47) {   // store next chunk -> other buf
            float* Aw = As[buf ^ 1]; float* Bw = Bs[buf ^ 1];
#pragma unroll
            for (int i = 0; i < 4; i++) {
                Aw[ar * 20 + 4 * i + aq]        = tf32r(a0v[i]);
                Aw[(ar + 64) * 20 + 4 * i + aq] = tf32r(a1v[i]);
            }
#pragma unroll
            for (int h = 0; h < 2; h++)
#pragma unroll
                for (int i = 0; i < 4; i++)
                    Bw[(bn0 + 64 * h) * 20 + 4 * i + bq] = tf32r(btv[h][i]);
        }
        __syncthreads();
        buf ^= 1;
    }
#pragma unroll
    for (int mt = 0; mt < 2; mt++) {
        int r0 = bm + wm * 32 + mt * 16 + lr;
#pragma unroll
        for (int nt = 0; nt < 8; nt++) {
            int cI = bn + wn * 64 + nt * 8 + 2 * lc;
            float b0 = bias[cI], b1 = bias[cI + 1];
            *(float2*)&Cm[(size_t)r0 * Nd + cI] =
                make_float2(acc[mt][nt][0] + b0, acc[mt][nt][1] + b1);
            *(float2*)&Cm[(size_t)(r0 + 8) * Nd + cI] =
                make_float2(acc[mt][nt][2] + b0, acc[mt][nt][3] + b1);
        }
    }
}

// ---------------- 8. flash attention, tf32 MMA, k-interleaved smem ----------------
// row stride 76 words; phys within 16-block: 16*(k>>4) + 4*(k&3) + ((k>>2)&3)
__global__ __launch_bounds__(256, 2) void flash_tf32_k(
        const float* __restrict__ qkv, float* __restrict__ o) {
    extern __shared__ float sm[];
    float* Qs = sm;               // [128][76]
    float* Ks = Qs + 128 * 76;    // [64][76]  K (n,k) then V^T (d,c)
    float* Ps = Ks + 64 * 76;     // [128][76]

    int qt = blockIdx.x, bh = blockIdx.y;
    int b = bh / HH, h = bh % HH;
    const float* base = qkv + (size_t)b * MM * C3 + h * 64;
    int tid = threadIdx.x;
    int w = tid >> 5, l = tid & 31;
    int lr = l >> 2, lc = l & 3;
    int mr0 = w * 16 + lr;

    {   // load Q (interleaved)
        int r = tid >> 1, hf = (tid & 1) * 32;
        const float* qp = base + (size_t)(qt * 128 + r) * C3 + hf;
#pragma unroll
        for (int i = 0; i < 8; i++) {
            float4 v = *(const float4*)(qp + i * 4);
            int Q = hf / 4 + i;
            int bw = r * 76 + (Q >> 2) * 16 + (Q & 3);
            Qs[bw + 0]  = tf32r(v.x);
            Qs[bw + 4]  = tf32r(v.y);
            Qs[bw + 8]  = tf32r(v.z);
            Qs[bw + 12] = tf32r(v.w);
        }
    }
    float om[8][4] = {};
    float m0 = -INFINITY, m1 = -INFINITY, l0 = 0.f, l1 = 0.f;

    for (int kt = 0; kt < 24; kt++) {
        __syncthreads();
        {   // load K tile (n,k interleaved)
            int r = tid >> 2, t3 = tid & 3;
            const float* kp = base + CC + (size_t)(kt * 64 + r) * C3 + t3 * 16;
#pragma unroll
            for (int i = 0; i < 4; i++) {
                float4 v = *(const float4*)(kp + i * 4);
                int bw = r * 76 + t3 * 16 + i;
                Ks[bw + 0]  = tf32r(v.x);
                Ks[bw + 4]  = tf32r(v.y);
                Ks[bw + 8]  = tf32r(v.z);
                Ks[bw + 12] = tf32r(v.w);
            }
        }
        __syncthreads();
        // S = Q K^T
        float s[8][4] = {};
#pragma unroll
        for (int blk = 0; blk < 4; blk++) {
            float4 f0 = *(const float4*)&Qs[mr0 * 76 + blk * 16 + 4 * lc];
            float4 f1 = *(const float4*)&Qs[(mr0 + 8) * 76 + blk * 16 + 4 * lc];
            unsigned a0[4] = {U(f0.x), U(f1.x), U(f0.y), U(f1.y)};
            unsigned a1[4] = {U(f0.z), U(f1.z), U(f0.w), U(f1.w)};
#pragma unroll
            for (int nt = 0; nt < 8; nt++) {
                float4 fb = *(const float4*)&Ks[(nt * 8 + lr) * 76 + blk * 16 + 4 * lc];
                unsigned b0[2] = {U(fb.x), U(fb.y)};
                unsigned b1[2] = {U(fb.z), U(fb.w)};
                mma8(s[nt], a0, b0);
                mma8(s[nt], a1, b1);
            }
        }
        // online softmax (verified in R4)
        float mx0 = -INFINITY, mx1 = -INFINITY;
#pragma unroll
        for (int nt = 0; nt < 8; nt++) {
            s[nt][0] *= 0.125f; s[nt][1] *= 0.125f;
            s[nt][2] *= 0.125f; s[nt][3] *= 0.125f;
            mx0 = fmaxf(mx0, fmaxf(s[nt][0], s[nt][1]));
            mx1 = fmaxf(mx1, fmaxf(s[nt][2], s[nt][3]));
        }
        mx0 = fmaxf(mx0, __shfl_xor_sync(0xffffffffu, mx0, 1));
        mx0 = fmaxf(mx0, __shfl_xor_sync(0xffffffffu, mx0, 2));
        mx1 = fmaxf(mx1, __shfl_xor_sync(0xffffffffu, mx1, 1));
        mx1 = fmaxf(mx1, __shfl_xor_sync(0xffffffffu, mx1, 2));
        float mn0 = fmaxf(m0, mx0), mn1 = fmaxf(m1, mx1);
        float al0 = __expf(m0 - mn0), al1 = __expf(m1 - mn1);
        m0 = mn0; m1 = mn1;
        float rs0 = 0.f, rs1 = 0.f;
#pragma unroll
        for (int nt = 0; nt < 8; nt++) {
            float p0 = __expf(s[nt][0] - mn0), p1 = __expf(s[nt][1] - mn0);
            float p2 = __expf(s[nt][2] - mn1), p3 = __expf(s[nt][3] - mn1);
            rs0 += p0 + p1; rs1 += p2 + p3;
            int c0 = nt * 8 + 2 * lc;
            int w0 = (c0 >> 4) * 16 + 4 * (c0 & 3) + ((c0 >> 2) & 3);
            int c1 = c0 + 1;
            int w1 = (c1 >> 4) * 16 + 4 * (c1 & 3) + ((c1 >> 2) & 3);
            Ps[mr0 * 76 + w0] = tf32r(p0);
            Ps[mr0 * 76 + w1] = tf32r(p1);
            Ps[(mr0 + 8) * 76 + w0] = tf32r(p2);
            Ps[(mr0 + 8) * 76 + w1] = tf32r(p3);
        }
        rs0 += __shfl_xor_sync(0xffffffffu, rs0, 1);
        rs0 += __shfl_xor_sync(0xffffffffu, rs0, 2);
        rs1 += __shfl_xor_sync(0xffffffffu, rs1, 1);
        rs1 += __shfl_xor_sync(0xffffffffu, rs1, 2);
        l0 = l0 * al0 + rs0; l1 = l1 * al1 + rs1;
#pragma unroll
        for (int nt = 0; nt < 8; nt++) {
            om[nt][0] *= al0; om[nt][1] *= al0;
            om[nt][2] *= al1; om[nt][3] *= al1;
        }
        __syncthreads();
        {   // load V transposed (d rows, c interleaved)
            int d = tid & 63, cb = (tid >> 6) * 16;
            const float* vp = base + 2 * CC + (size_t)(kt * 64 + cb) * C3 + d;
#pragma unroll
            for (int i = 0; i < 16; i++) {
                int cw = cb + 4 * (i & 3) + (i >> 2);
                Ks[d * 76 + cw] = tf32r(vp[(size_t)i * C3]);
            }
        }
        __syncthreads();
        // O += P V
#pragma unroll
        for (int blk = 0; blk < 4; blk++) {
            float4 f0 = *(const float4*)&Ps[mr0 * 76 + blk * 16 + 4 * lc];
            float4 f1 = *(const float4*)&Ps[(mr0 + 8) * 76 + blk * 16 + 4 * lc];
            unsigned a0[4] = {U(f0.x), U(f1.x), U(f0.y), U(f1.y)};
            unsigned a1[4] = {U(f0.z), U(f1.z), U(f0.w), U(f1.w)};
#pragma unroll
            for (int nt = 0; nt < 8; nt++) {
                float4 fb = *(const float4*)&Ks[(nt * 8 + lr) * 76 + blk * 16 + 4 * lc];
                unsigned b0[2] = {U(fb.x), U(fb.y)};
                unsigned b1[2] = {U(fb.z), U(fb.w)};
                mma8(om[nt], a0, b0);
                mma8(om[nt], a1, b1);
            }
        }
    }
    float i0 = 1.f / l0, i1 = 1.f / l1;
    size_t row0 = (size_t)b * MM + qt * 128 + mr0;
#pragma unroll
    for (int nt = 0; nt < 8; nt++) {
        int c = h * 64 + nt * 8 + 2 * lc;
        *(float2*)&o[row0 * CC + c]       = make_float2(om[nt][0] * i0, om[nt][1] * i0);
        *(float2*)&o[(row0 + 8) * CC + c] = make_float2(om[nt][2] * i1, om[nt][3] * i1);
    }
}

// ---------------- 9. unmerge (unchanged) ----------------
__global__ void unmerge_k(float* __restrict__ out) {
    int row = blockIdx.x;
    int b = row >> 11;
    int n = row & 2047;
    int yrow = (n & 1) ? (n >> 1) : g_gather[b * NSRC + (n >> 1)];
    const float* src = g_y + ((size_t)b * MM + yrow) * CC;
    float* dst = out + (size_t)row * CC;
    int t = threadIdx.x;                  // 192
    *(float4*)&dst[t * 4] = *(const float4*)&src[t * 4];
}

// ---------------- launcher ----------------
extern "C" void kernel_launch(void* const* d_in, const int* in_sizes, int n_in,
                              void* d_out, int out_size) {
    const float* x    = (const float*)d_in[0];
    const float* Wqkv = (const float*)d_in[1];
    const float* bqkv = (const float*)d_in[2];
    const float* Wo   = (const float*)d_in[3];
    const float* bo   = (const float*)d_in[4];
    float* out = (float*)d_out;

    float *xm, *qkvb, *attnb, *yb;
    cudaGetSymbolAddress((void**)&xm, g_xm);
    cudaGetSymbolAddress((void**)&qkvb, g_qkv);
    cudaGetSymbolAddress((void**)&attnb, g_attn);
    cudaGetSymbolAddress((void**)&yb, g_y);

    cudaFuncSetAttribute(flash_tf32_k, cudaFuncAttributeMaxDynamicSharedMemorySize, 97280);

    metric_k<<<BB * NN, 256>>>(x);
    match128_k<<<dim3(8, 8, 8), 256>>>();
    matchred_k<<<32, 256>>>();
    topk_k<<<BB, 1024>>>();
    build_xm_k<<<BB * MM, 192>>>(x);
    merge_add_k<<<BB * RR, 192>>>(x);
    divide_k<<<BB * NDST, 192>>>();
    gemm_tf32_k<<<dim3(C3 / 128, (BB * MM) / 128), 256>>>(xm, Wqkv, bqkv, qkvb, C3);
    flash_tf32_k<<<dim3(MM / 128, BB * HH), 256, 97280>>>(qkvb, attnb);
    gemm_tf32_k<<<dim3(CC / 128, (BB * MM) / 128), 256>>>(attnb, Wo, bo, yb, CC);
    unmerge_k<<<BB * NN, 192>>>(out);
}

// round 6
// speedup vs baseline: 1.1992x; 1.1992x over previous
#include <cuda_runtime.h>
#include <math.h>

#define BB 8
#define NN 2048
#define CC 768
#define HH 12
#define MM 1536
#define RR 512
#define NSRC 1024
#define NDST 1024
#define C3 2304

__device__ __forceinline__ float tf32r(float x) {
    unsigned r; asm("cvt.rna.tf32.f32 %0, %1;" : "=r"(r) : "f"(x));
    return __uint_as_float(r);
}
__device__ __forceinline__ void mma8(float c[4], const unsigned a[4], const unsigned b[2]) {
    asm volatile("mma.sync.aligned.m16n8k8.row.col.f32.tf32.tf32.f32 "
        "{%0,%1,%2,%3}, {%4,%5,%6,%7}, {%8,%9}, {%0,%1,%2,%3};"
        : "+f"(c[0]), "+f"(c[1]), "+f"(c[2]), "+f"(c[3])
        : "r"(a[0]), "r"(a[1]), "r"(a[2]), "r"(a[3]), "r"(b[0]), "r"(b[1]));
}
#define U(x) __float_as_uint(x)

// ---------------- scratch ----------------
__device__ float g_metric[(size_t)BB * NN * CC];
__device__ float g_pmax[BB * 8 * NSRC];
__device__ int   g_pidx[BB * 8 * NSRC];
__device__ int   g_srcidx[BB * RR];
__device__ int   g_unmidx[BB * RR];
__device__ int   g_gather[BB * NSRC];
__device__ int   g_lhead[BB * NSRC];
__device__ int   g_lnext[BB * RR];
__device__ float g_xm[(size_t)BB * MM * CC];
__device__ float g_qkv[(size_t)BB * MM * C3];
__device__ float g_attn[(size_t)BB * MM * CC];
__device__ float g_y[(size_t)BB * MM * CC];

// ---------------- 1. normalized metric (exact fp32, single pass) ----------------
__global__ void metric_k(const float* __restrict__ x) {
    int row = blockIdx.x;
    int tid = threadIdx.x;                 // 256
    const float* p = x + (size_t)row * CC;
    float* q = g_metric + (size_t)row * CC;
    float v0 = p[tid], v1 = p[tid + 256], v2 = p[tid + 512];
    float s = v0 * v0 + v1 * v1 + v2 * v2;
    __shared__ float red[256];
    red[tid] = s; __syncthreads();
    for (int o = 128; o > 0; o >>= 1) {
        if (tid < o) red[tid] += red[tid + o];
        __syncthreads();
    }
    float nrm = sqrtf(red[0]);
    q[tid] = v0 / nrm; q[tid + 256] = v1 / nrm; q[tid + 512] = v2 / nrm;
}

// ---------------- 2. matching scores, fp32-exact (verified) ----------------
__global__ __launch_bounds__(256, 2) void match128_k() {
    __shared__ float As[8][132];
    __shared__ float Bs[8][132];
    int dt = blockIdx.x, st = blockIdx.y, b = blockIdx.z;
    const float* mb = g_metric + (size_t)b * NN * CC;
    int tid = threadIdx.x;
    int tx = tid & 15, ty = tid >> 4;
    int lm = tid & 127, kq = (tid >> 7) * 4;
    const float* arow = mb + (size_t)(2 * (st * 128 + lm)) * CC + kq;
    const float* brow = mb + (size_t)(2 * (dt * 128 + lm) + 1) * CC + kq;
    float acc[8][8] = {};

    for (int k0 = 0; k0 < CC; k0 += 8) {
        float4 av = *(const float4*)(arow + k0);
        float4 bv = *(const float4*)(brow + k0);
        As[kq + 0][lm] = av.x; As[kq + 1][lm] = av.y;
        As[kq + 2][lm] = av.z; As[kq + 3][lm] = av.w;
        Bs[kq + 0][lm] = bv.x; Bs[kq + 1][lm] = bv.y;
        Bs[kq + 2][lm] = bv.z; Bs[kq + 3][lm] = bv.w;
        __syncthreads();
#pragma unroll
        for (int kk = 0; kk < 8; kk++) {
            float4 a0 = *(const float4*)&As[kk][ty * 8];
            float4 a1 = *(const float4*)&As[kk][ty * 8 + 4];
            float4 b0 = *(const float4*)&Bs[kk][tx * 8];
            float4 b1 = *(const float4*)&Bs[kk][tx * 8 + 4];
            float am[8] = {a0.x, a0.y, a0.z, a0.w, a1.x, a1.y, a1.z, a1.w};
            float bm[8] = {b0.x, b0.y, b0.z, b0.w, b1.x, b1.y, b1.z, b1.w};
#pragma unroll
            for (int i = 0; i < 8; i++)
#pragma unroll
                for (int j = 0; j < 8; j++)
                    acc[i][j] += am[i] * bm[j];
        }
        __syncthreads();
    }
#pragma unroll
    for (int i = 0; i < 8; i++) {
        float bv = acc[i][0]; int bj = 0;
#pragma unroll
        for (int j = 1; j < 8; j++)
            if (acc[i][j] > bv) { bv = acc[i][j]; bj = j; }
        int bi = dt * 128 + tx * 8 + bj;
        for (int off = 8; off; off >>= 1) {
            float ov = __shfl_xor_sync(0xffffffffu, bv, off);
            int   oi = __shfl_xor_sync(0xffffffffu, bi, off);
            if (ov > bv || (ov == bv && oi < bi)) { bv = ov; bi = oi; }
        }
        if (tx == 0) {
            int r = st * 128 + ty * 8 + i;
            g_pmax[(b * 8 + dt) * NSRC + r] = bv;
            g_pidx[(b * 8 + dt) * NSRC + r] = bi;
        }
    }
}

// ---------------- 3. top-k (fused partial-reduce + bitonic + lists) ----------------
__global__ void topk_k() {
    __shared__ unsigned long long key[1024];
    __shared__ int nidx[1024];
    __shared__ int mrg[1024];
    __shared__ int scn[1024];
    int b = blockIdx.x, tid = threadIdx.x;   // 1024

    // fused matchred: 8-way partial max (first-occurrence tie via > )
    float bv = g_pmax[(b * 8) * NSRC + tid];
    int   bi = g_pidx[(b * 8) * NSRC + tid];
#pragma unroll
    for (int dt = 1; dt < 8; dt++) {
        float v = g_pmax[(b * 8 + dt) * NSRC + tid];
        if (v > bv) { bv = v; bi = g_pidx[(b * 8 + dt) * NSRC + tid]; }
    }
    nidx[tid] = bi;
    {
        unsigned u = __float_as_uint(bv);
        u = (u & 0x80000000u) ? ~u : (u | 0x80000000u);
        key[tid] = ((unsigned long long)(~u) << 32) | (unsigned)tid;
    }
    mrg[tid] = 0;
    g_lhead[b * NSRC + tid] = -1;
    __syncthreads();
    for (int k = 2; k <= 1024; k <<= 1)
        for (int j = k >> 1; j > 0; j >>= 1) {
            int p = tid ^ j;
            if (p > tid) {
                bool up = ((tid & k) == 0);
                unsigned long long a = key[tid], c2 = key[p];
                if ((a > c2) == up) { key[tid] = c2; key[p] = a; }
            }
            __syncthreads();
        }
    if (tid < 512) {
        int s = (int)(key[tid] & 0xffffffffu);
        g_srcidx[b * RR + tid] = s;
        mrg[s] = 1;
        int d = nidx[s];
        g_lnext[b * RR + tid] = atomicExch(&g_lhead[b * NSRC + d], tid);
    }
    __syncthreads();
    int um = mrg[tid] ? 0 : 1;
    scn[tid] = um; __syncthreads();
    for (int off = 1; off < 1024; off <<= 1) {
        int v = scn[tid];
        int v2 = (tid >= off) ? scn[tid - off] : 0;
        __syncthreads();
        scn[tid] = v + v2; __syncthreads();
    }
    int rnk = scn[tid] - um;
    if (um) { g_unmidx[b * RR + rnk] = tid; g_gather[b * NSRC + tid] = NDST + rnk; }
    else    { g_gather[b * NSRC + tid] = nidx[tid]; }
}

// ---------------- 4. fused merge build: gather + list-sum + divide ----------------
__global__ void buildall_k(const float* __restrict__ x) {
    int row = blockIdx.x;                   // 0..B*MM-1
    int b = row / MM, j = row - b * MM;
    int t = threadIdx.x;                    // 192
    float* dst = g_xm + (size_t)row * CC;
    if (j >= NDST) {
        int s = g_unmidx[b * RR + (j - NDST)];
        const float* src = x + ((size_t)b * NN + 2 * s) * CC;
        *(float4*)&dst[t * 4] = *(const float4*)&src[t * 4];
        return;
    }
    const float* dsrc = x + ((size_t)b * NN + 2 * j + 1) * CC;
    float4 v = *(const float4*)&dsrc[t * 4];
    float cntf = 1.f;
    int it = g_lhead[b * NSRC + j];
    while (it >= 0) {
        int s = g_srcidx[b * RR + it];
        float4 sv = *(const float4*)&x[((size_t)b * NN + 2 * s) * CC + t * 4];
        v.x += sv.x; v.y += sv.y; v.z += sv.z; v.w += sv.w;
        cntf += 1.f;
        it = g_lnext[b * RR + it];
    }
    float inv = 1.f / cntf;
    v.x *= inv; v.y *= inv; v.z *= inv; v.w *= inv;
    *(float4*)&dst[t * 4] = v;
}

// ---------------- 5. tf32 GEMM (R4-verified version) ----------------
__global__ __launch_bounds__(256, 2) void gemm_tf32_k(
        const float* __restrict__ A, const float* __restrict__ Bm,
        const float* __restrict__ bias, float* __restrict__ Cm, int Nd, int Kd) {
    __shared__ float As[128 * 20];   // [m][k] pad 20
    __shared__ float Bs[128 * 20];   // [n][k] pad 20
    int tid = threadIdx.x;
    int w = tid >> 5, l = tid & 31;
    int wm = w & 3, wn = w >> 2;
    int lr = l >> 2, lc = l & 3;
    int bm = blockIdx.y * 128, bn = blockIdx.x * 128;
    float acc[2][8][4] = {};

    int ar = tid >> 2, ak = (tid & 3) * 4;
    int bnn = tid & 127, bk = (tid >> 7) * 8;
    const float* Ap0 = A + (size_t)(bm + ar) * Kd + ak;
    const float* Ap1 = A + (size_t)(bm + ar + 64) * Kd + ak;
    const float* Bp  = Bm + bn + bnn;

    float4 a0v = *(const float4*)Ap0;
    float4 a1v = *(const float4*)Ap1;
    float btmp[8];
#pragma unroll
    for (int j = 0; j < 8; j++) btmp[j] = Bp[(size_t)(bk + j) * Nd];

    for (int k0 = 0; k0 < Kd; k0 += 16) {
        *(float4*)&As[ar * 20 + ak] =
            make_float4(tf32r(a0v.x), tf32r(a0v.y), tf32r(a0v.z), tf32r(a0v.w));
        *(float4*)&As[(ar + 64) * 20 + ak] =
            make_float4(tf32r(a1v.x), tf32r(a1v.y), tf32r(a1v.z), tf32r(a1v.w));
        *(float4*)&Bs[bnn * 20 + bk] =
            make_float4(tf32r(btmp[0]), tf32r(btmp[1]), tf32r(btmp[2]), tf32r(btmp[3]));
        *(float4*)&Bs[bnn * 20 + bk + 4] =
            make_float4(tf32r(btmp[4]), tf32r(btmp[5]), tf32r(btmp[6]), tf32r(btmp[7]));
        __syncthreads();
        if (k0 + 16 < Kd) {
            a0v = *(const float4*)(Ap0 + k0 + 16);
            a1v = *(const float4*)(Ap1 + k0 + 16);
#pragma unroll
            for (int j = 0; j < 8; j++) btmp[j] = Bp[(size_t)(k0 + 16 + bk + j) * Nd];
        }
#pragma unroll
        for (int ks = 0; ks < 2; ks++) {
            int kc = ks * 8 + lc;
            unsigned af[2][4];
#pragma unroll
            for (int mt = 0; mt < 2; mt++) {
                int mr = wm * 32 + mt * 16 + lr;
                af[mt][0] = U(As[mr * 20 + kc]);
                af[mt][1] = U(As[(mr + 8) * 20 + kc]);
                af[mt][2] = U(As[mr * 20 + kc + 4]);
                af[mt][3] = U(As[(mr + 8) * 20 + kc + 4]);
            }
#pragma unroll
            for (int nt = 0; nt < 8; nt++) {
                int nc = wn * 64 + nt * 8 + lr;
                unsigned bf[2] = { U(Bs[nc * 20 + kc]), U(Bs[nc * 20 + kc + 4]) };
                mma8(acc[0][nt], af[0], bf);
                mma8(acc[1][nt], af[1], bf);
            }
        }
        __syncthreads();
    }
#pragma unroll
    for (int mt = 0; mt < 2; mt++) {
        int r0 = bm + wm * 32 + mt * 16 + lr;
#pragma unroll
        for (int nt = 0; nt < 8; nt++) {
            int c = bn + wn * 64 + nt * 8 + 2 * lc;
            float b0 = bias[c], b1 = bias[c + 1];
            *(float2*)&Cm[(size_t)r0 * Nd + c] =
                make_float2(acc[mt][nt][0] + b0, acc[mt][nt][1] + b1);
            *(float2*)&Cm[(size_t)(r0 + 8) * Nd + c] =
                make_float2(acc[mt][nt][2] + b0, acc[mt][nt][3] + b1);
        }
    }
}

// ---------------- 6. flash attention (R4 layout + separate V buffer, 3 syncs) ----------------
__global__ __launch_bounds__(256, 2) void flash_tf32_k(
        const float* __restrict__ qkv, float* __restrict__ o) {
    extern __shared__ float sm[];
    float* Qs = sm;               // [128][68]  (m,k), pre-scaled by 0.125
    float* Ks = Qs + 128 * 68;    // [64][68]   K (n,k)
    float* Vs = Ks + 64 * 68;     // [64][68]   V^T (d,c)
    float* Ps = Vs + 64 * 68;     // [128][68]

    int qt = blockIdx.x, bh = blockIdx.y;
    int b = bh / HH, h = bh % HH;
    const float* base = qkv + (size_t)b * MM * C3 + h * 64;
    int tid = threadIdx.x;
    int w = tid >> 5, l = tid & 31;
    int lr = l >> 2, lc = l & 3;
    int mr0 = w * 16 + lr;

    {   // load Q once, fold in softmax scale (exact: *2^-3)
        int r = tid >> 1, hf = (tid & 1) * 32;
        const float* qp = base + (size_t)(qt * 128 + r) * C3 + hf;
#pragma unroll
        for (int i = 0; i < 8; i++) {
            float4 v = *(const float4*)(qp + i * 4);
            *(float4*)&Qs[r * 68 + hf + i * 4] =
                make_float4(tf32r(v.x * 0.125f), tf32r(v.y * 0.125f),
                            tf32r(v.z * 0.125f), tf32r(v.w * 0.125f));
        }
    }
    float om[8][4] = {};
    float m0 = -INFINITY, m1 = -INFINITY, l0 = 0.f, l1 = 0.f;

    for (int kt = 0; kt < 24; kt++) {
        __syncthreads();                    // prev S read Ks done; prev O read Vs/Ps done
        {   // load K tile (n,k)
            int r = tid >> 2, qq = (tid & 3) * 16;
            const float* kp = base + CC + (size_t)(kt * 64 + r) * C3 + qq;
#pragma unroll
            for (int i = 0; i < 4; i++) {
                float4 v = *(const float4*)(kp + i * 4);
                *(float4*)&Ks[r * 68 + qq + i * 4] =
                    make_float4(tf32r(v.x), tf32r(v.y), tf32r(v.z), tf32r(v.w));
            }
        }
        {   // load V transposed: Vt[d][c]
            int d = tid & 63, cb = (tid >> 6) * 16;
            const float* vp = base + 2 * CC + (size_t)(kt * 64 + cb) * C3 + d;
#pragma unroll
            for (int i = 0; i < 16; i++)
                Vs[d * 68 + cb + i] = tf32r(vp[(size_t)i * C3]);
        }
        __syncthreads();
        // S = Q K^T (already scaled)
        float s[8][4] = {};
#pragma unroll
        for (int ks = 0; ks < 8; ks++) {
            int kb = ks * 8 + lc;
            unsigned af[4];
            af[0] = U(Qs[mr0 * 68 + kb]);
            af[1] = U(Qs[(mr0 + 8) * 68 + kb]);
            af[2] = U(Qs[mr0 * 68 + kb + 4]);
            af[3] = U(Qs[(mr0 + 8) * 68 + kb + 4]);
#pragma unroll
            for (int nt = 0; nt < 8; nt++) {
                int nc = nt * 8 + lr;
                unsigned bf[2] = { U(Ks[nc * 68 + kb]), U(Ks[nc * 68 + kb + 4]) };
                mma8(s[nt], af, bf);
            }
        }
        // online softmax
        float mx0 = -INFINITY, mx1 = -INFINITY;
#pragma unroll
        for (int nt = 0; nt < 8; nt++) {
            mx0 = fmaxf(mx0, fmaxf(s[nt][0], s[nt][1]));
            mx1 = fmaxf(mx1, fmaxf(s[nt][2], s[nt][3]));
        }
        mx0 = fmaxf(mx0, __shfl_xor_sync(0xffffffffu, mx0, 1));
        mx0 = fmaxf(mx0, __shfl_xor_sync(0xffffffffu, mx0, 2));
        mx1 = fmaxf(mx1, __shfl_xor_sync(0xffffffffu, mx1, 1));
        mx1 = fmaxf(mx1, __shfl_xor_sync(0xffffffffu, mx1, 2));
        float mn0 = fmaxf(m0, mx0), mn1 = fmaxf(m1, mx1);
        float al0 = __expf(m0 - mn0), al1 = __expf(m1 - mn1);
        m0 = mn0; m1 = mn1;
        float rs0 = 0.f, rs1 = 0.f;
#pragma unroll
        for (int nt = 0; nt < 8; nt++) {
            float p0 = __expf(s[nt][0] - mn0), p1 = __expf(s[nt][1] - mn0);
            float p2 = __expf(s[nt][2] - mn1), p3 = __expf(s[nt][3] - mn1);
            rs0 += p0 + p1; rs1 += p2 + p3;
            int c = nt * 8 + 2 * lc;
            *(float2*)&Ps[mr0 * 68 + c]       = make_float2(tf32r(p0), tf32r(p1));
            *(float2*)&Ps[(mr0 + 8) * 68 + c] = make_float2(tf32r(p2), tf32r(p3));
        }
        rs0 += __shfl_xor_sync(0xffffffffu, rs0, 1);
        rs0 += __shfl_xor_sync(0xffffffffu, rs0, 2);
        rs1 += __shfl_xor_sync(0xffffffffu, rs1, 1);
        rs1 += __shfl_xor_sync(0xffffffffu, rs1, 2);
        l0 = l0 * al0 + rs0; l1 = l1 * al1 + rs1;
#pragma unroll
        for (int nt = 0; nt < 8; nt++) {
            om[nt][0] *= al0; om[nt][1] *= al0;
            om[nt][2] *= al1; om[nt][3] *= al1;
        }
        __syncthreads();                    // Ps visible (Vs visible since load sync)
        // O += P V
#pragma unroll
        for (int ks = 0; ks < 8; ks++) {
            int kb = ks * 8 + lc;
            unsigned af[4];
            af[0] = U(Ps[mr0 * 68 + kb]);
            af[1] = U(Ps[(mr0 + 8) * 68 + kb]);
            af[2] = U(Ps[mr0 * 68 + kb + 4]);
            af[3] = U(Ps[(mr0 + 8) * 68 + kb + 4]);
#pragma unroll
            for (int nt = 0; nt < 8; nt++) {
                int nc = nt * 8 + lr;
                unsigned bf[2] = { U(Vs[nc * 68 + kb]), U(Vs[nc * 68 + kb + 4]) };
                mma8(om[nt], af, bf);
            }
        }
    }
    float i0 = 1.f / l0, i1 = 1.f / l1;
    size_t row0 = (size_t)b * MM + qt * 128 + mr0;
#pragma unroll
    for (int nt = 0; nt < 8; nt++) {
        int c = h * 64 + nt * 8 + 2 * lc;
        *(float2*)&o[row0 * CC + c]       = make_float2(om[nt][0] * i0, om[nt][1] * i0);
        *(float2*)&o[(row0 + 8) * CC + c] = make_float2(om[nt][2] * i1, om[nt][3] * i1);
    }
}

// ---------------- 7. unmerge ----------------
__global__ void unmerge_k(float* __restrict__ out) {
    int row = blockIdx.x;
    int b = row >> 11;
    int n = row & 2047;
    int yrow = (n & 1) ? (n >> 1) : g_gather[b * NSRC + (n >> 1)];
    const float* src = g_y + ((size_t)b * MM + yrow) * CC;
    float* dst = out + (size_t)row * CC;
    int t = threadIdx.x;                  // 192
    *(float4*)&dst[t * 4] = *(const float4*)&src[t * 4];
}

// ---------------- launcher ----------------
extern "C" void kernel_launch(void* const* d_in, const int* in_sizes, int n_in,
                              void* d_out, int out_size) {
    const float* x    = (const float*)d_in[0];
    const float* Wqkv = (const float*)d_in[1];
    const float* bqkv = (const float*)d_in[2];
    const float* Wo   = (const float*)d_in[3];
    const float* bo   = (const float*)d_in[4];
    float* out = (float*)d_out;

    float *xm, *qkvb, *attnb, *yb;
    cudaGetSymbolAddress((void**)&xm, g_xm);
    cudaGetSymbolAddress((void**)&qkvb, g_qkv);
    cudaGetSymbolAddress((void**)&attnb, g_attn);
    cudaGetSymbolAddress((void**)&yb, g_y);

    cudaFuncSetAttribute(flash_tf32_k, cudaFuncAttributeMaxDynamicSharedMemorySize, 104448);

    metric_k<<<BB * NN, 256>>>(x);
    match128_k<<<dim3(8, 8, 8), 256>>>();
    topk_k<<<BB, 1024>>>();
    buildall_k<<<BB * MM, 192>>>(x);
    gemm_tf32_k<<<dim3(C3 / 128, (BB * MM) / 128), 256>>>(xm, Wqkv, bqkv, qkvb, C3, CC);
    flash_tf32_k<<<dim3(MM / 128, BB * HH), 256, 104448>>>(qkvb, attnb);
    gemm_tf32_k<<<dim3(CC / 128, (BB * MM) / 128), 256>>>(attnb, Wo, bo, yb, CC, CC);
    unmerge_k<<<BB * NN, 192>>>(out);
}

// round 7
// speedup vs baseline: 1.2919x; 1.0773x over previous
#include <cuda_runtime.h>
#include <math.h>

#define BB 8
#define NN 2048
#define CC 768
#define HH 12
#define MM 1536
#define RR 512
#define NSRC 1024
#define NDST 1024
#define C3 2304

__device__ __forceinline__ float tf32r(float x) {
    unsigned r; asm("cvt.rna.tf32.f32 %0, %1;" : "=r"(r) : "f"(x));
    return __uint_as_float(r);
}
__device__ __forceinline__ void mma8(float c[4], const unsigned a[4], const unsigned b[2]) {
    asm volatile("mma.sync.aligned.m16n8k8.row.col.f32.tf32.tf32.f32 "
        "{%0,%1,%2,%3}, {%4,%5,%6,%7}, {%8,%9}, {%0,%1,%2,%3};"
        : "+f"(c[0]), "+f"(c[1]), "+f"(c[2]), "+f"(c[3])
        : "r"(a[0]), "r"(a[1]), "r"(a[2]), "r"(a[3]), "r"(b[0]), "r"(b[1]));
}
// ldmatrix x4 (b16 path, valid for tf32 4-byte elements): thread l gets element
// [l>>2][l&3] of each 8x4-tf32 matrix; lanes 0-7/8-15/16-23/24-31 supply row addrs.
__device__ __forceinline__ void ldsm4(unsigned r[4], unsigned addr) {
    asm volatile("ldmatrix.sync.aligned.m8n8.x4.shared.b16 {%0,%1,%2,%3}, [%4];"
        : "=r"(r[0]), "=r"(r[1]), "=r"(r[2]), "=r"(r[3]) : "r"(addr));
}
__device__ __forceinline__ unsigned smem_u32(const void* p) {
    return (unsigned)__cvta_generic_to_shared(p);
}

// ---------------- scratch ----------------
__device__ float g_metric[(size_t)BB * NN * CC];
__device__ float g_pmax[BB * 8 * NSRC];
__device__ int   g_pidx[BB * 8 * NSRC];
__device__ int   g_srcidx[BB * RR];
__device__ int   g_unmidx[BB * RR];
__device__ int   g_gather[BB * NSRC];
__device__ int   g_lhead[BB * NSRC];
__device__ int   g_lnext[BB * RR];
__device__ float g_xm[(size_t)BB * MM * CC];
__device__ float g_qkv[(size_t)BB * MM * C3];
__device__ float g_attn[(size_t)BB * MM * CC];
__device__ float g_y[(size_t)BB * MM * CC];

// ---------------- 1. normalized metric ----------------
__global__ void metric_k(const float* __restrict__ x) {
    int row = blockIdx.x;
    int tid = threadIdx.x;                 // 256
    const float* p = x + (size_t)row * CC;
    float* q = g_metric + (size_t)row * CC;
    float v0 = p[tid], v1 = p[tid + 256], v2 = p[tid + 512];
    float s = v0 * v0 + v1 * v1 + v2 * v2;
    __shared__ float red[256];
    red[tid] = s; __syncthreads();
    for (int o = 128; o > 0; o >>= 1) {
        if (tid < o) red[tid] += red[tid + o];
        __syncthreads();
    }
    float nrm = sqrtf(red[0]);
    q[tid] = v0 / nrm; q[tid + 256] = v1 / nrm; q[tid + 512] = v2 / nrm;
}

// ---------------- 2. matching scores, fp32-exact (verified) ----------------
__global__ __launch_bounds__(256, 2) void match128_k() {
    __shared__ float As[8][132];
    __shared__ float Bs[8][132];
    int dt = blockIdx.x, st = blockIdx.y, b = blockIdx.z;
    const float* mb = g_metric + (size_t)b * NN * CC;
    int tid = threadIdx.x;
    int tx = tid & 15, ty = tid >> 4;
    int lm = tid & 127, kq = (tid >> 7) * 4;
    const float* arow = mb + (size_t)(2 * (st * 128 + lm)) * CC + kq;
    const float* brow = mb + (size_t)(2 * (dt * 128 + lm) + 1) * CC + kq;
    float acc[8][8] = {};

    for (int k0 = 0; k0 < CC; k0 += 8) {
        float4 av = *(const float4*)(arow + k0);
        float4 bv = *(const float4*)(brow + k0);
        As[kq + 0][lm] = av.x; As[kq + 1][lm] = av.y;
        As[kq + 2][lm] = av.z; As[kq + 3][lm] = av.w;
        Bs[kq + 0][lm] = bv.x; Bs[kq + 1][lm] = bv.y;
        Bs[kq + 2][lm] = bv.z; Bs[kq + 3][lm] = bv.w;
        __syncthreads();
#pragma unroll
        for (int kk = 0; kk < 8; kk++) {
            float4 a0 = *(const float4*)&As[kk][ty * 8];
            float4 a1 = *(const float4*)&As[kk][ty * 8 + 4];
            float4 b0 = *(const float4*)&Bs[kk][tx * 8];
            float4 b1 = *(const float4*)&Bs[kk][tx * 8 + 4];
            float am[8] = {a0.x, a0.y, a0.z, a0.w, a1.x, a1.y, a1.z, a1.w};
            float bm[8] = {b0.x, b0.y, b0.z, b0.w, b1.x, b1.y, b1.z, b1.w};
#pragma unroll
            for (int i = 0; i < 8; i++)
#pragma unroll
                for (int j = 0; j < 8; j++)
                    acc[i][j] += am[i] * bm[j];
        }
        __syncthreads();
    }
#pragma unroll
    for (int i = 0; i < 8; i++) {
        float bv = acc[i][0]; int bj = 0;
#pragma unroll
        for (int j = 1; j < 8; j++)
            if (acc[i][j] > bv) { bv = acc[i][j]; bj = j; }
        int bi = dt * 128 + tx * 8 + bj;
        for (int off = 8; off; off >>= 1) {
            float ov = __shfl_xor_sync(0xffffffffu, bv, off);
            int   oi = __shfl_xor_sync(0xffffffffu, bi, off);
            if (ov > bv || (ov == bv && oi < bi)) { bv = ov; bi = oi; }
        }
        if (tx == 0) {
            int r = st * 128 + ty * 8 + i;
            g_pmax[(b * 8 + dt) * NSRC + r] = bv;
            g_pidx[(b * 8 + dt) * NSRC + r] = bi;
        }
    }
}

// ---------------- 3. top-k (fused partial-reduce + bitonic + lists) ----------------
__global__ void topk_k() {
    __shared__ unsigned long long key[1024];
    __shared__ int nidx[1024];
    __shared__ int mrg[1024];
    __shared__ int scn[1024];
    int b = blockIdx.x, tid = threadIdx.x;   // 1024

    float bv = g_pmax[(b * 8) * NSRC + tid];
    int   bi = g_pidx[(b * 8) * NSRC + tid];
#pragma unroll
    for (int dt = 1; dt < 8; dt++) {
        float v = g_pmax[(b * 8 + dt) * NSRC + tid];
        if (v > bv) { bv = v; bi = g_pidx[(b * 8 + dt) * NSRC + tid]; }
    }
    nidx[tid] = bi;
    {
        unsigned u = __float_as_uint(bv);
        u = (u & 0x80000000u) ? ~u : (u | 0x80000000u);
        key[tid] = ((unsigned long long)(~u) << 32) | (unsigned)tid;
    }
    mrg[tid] = 0;
    g_lhead[b * NSRC + tid] = -1;
    __syncthreads();
    for (int k = 2; k <= 1024; k <<= 1)
        for (int j = k >> 1; j > 0; j >>= 1) {
            int p = tid ^ j;
            if (p > tid) {
                bool up = ((tid & k) == 0);
                unsigned long long a = key[tid], c2 = key[p];
                if ((a > c2) == up) { key[tid] = c2; key[p] = a; }
            }
            __syncthreads();
        }
    if (tid < 512) {
        int s = (int)(key[tid] & 0xffffffffu);
        g_srcidx[b * RR + tid] = s;
        mrg[s] = 1;
        int d = nidx[s];
        g_lnext[b * RR + tid] = atomicExch(&g_lhead[b * NSRC + d], tid);
    }
    __syncthreads();
    int um = mrg[tid] ? 0 : 1;
    scn[tid] = um; __syncthreads();
    for (int off = 1; off < 1024; off <<= 1) {
        int v = scn[tid];
        int v2 = (tid >= off) ? scn[tid - off] : 0;
        __syncthreads();
        scn[tid] = v + v2; __syncthreads();
    }
    int rnk = scn[tid] - um;
    if (um) { g_unmidx[b * RR + rnk] = tid; g_gather[b * NSRC + tid] = NDST + rnk; }
    else    { g_gather[b * NSRC + tid] = nidx[tid]; }
}

// ---------------- 4. fused merge build ----------------
__global__ void buildall_k(const float* __restrict__ x) {
    int row = blockIdx.x;                   // 0..B*MM-1
    int b = row / MM, j = row - b * MM;
    int t = threadIdx.x;                    // 192
    float* dst = g_xm + (size_t)row * CC;
    if (j >= NDST) {
        int s = g_unmidx[b * RR + (j - NDST)];
        const float* src = x + ((size_t)b * NN + 2 * s) * CC;
        *(float4*)&dst[t * 4] = *(const float4*)&src[t * 4];
        return;
    }
    const float* dsrc = x + ((size_t)b * NN + 2 * j + 1) * CC;
    float4 v = *(const float4*)&dsrc[t * 4];
    float cntf = 1.f;
    int it = g_lhead[b * NSRC + j];
    while (it >= 0) {
        int s = g_srcidx[b * RR + it];
        float4 sv = *(const float4*)&x[((size_t)b * NN + 2 * s) * CC + t * 4];
        v.x += sv.x; v.y += sv.y; v.z += sv.z; v.w += sv.w;
        cntf += 1.f;
        it = g_lnext[b * RR + it];
    }
    float inv = 1.f / cntf;
    v.x *= inv; v.y *= inv; v.z *= inv; v.w *= inv;
    *(float4*)&dst[t * 4] = v;
}

// ---------------- 5. tf32 GEMM: R6 layout + ldmatrix fragment loads ----------------
__global__ __launch_bounds__(256, 2) void gemm_tf32_k(
        const float* __restrict__ A, const float* __restrict__ Bm,
        const float* __restrict__ bias, float* __restrict__ Cm, int Nd, int Kd) {
    __shared__ float As[128 * 20];   // [m][k] pad 20
    __shared__ float Bs[128 * 20];   // [n][k] pad 20
    int tid = threadIdx.x;
    int w = tid >> 5, l = tid & 31;
    int wm = w & 3, wn = w >> 2;
    int lr = l >> 2, lc = l & 3;
    int bm = blockIdx.y * 128, bn = blockIdx.x * 128;
    float acc[2][8][4] = {};

    // ldmatrix lane addressing (loop-invariant):
    // A: lanes 0-7 rows+k0 | 8-15 rows+8,k0 | 16-23 rows,k4 | 24-31 rows+8,k4
    int arow_a = (l & 7) + ((l >> 3) & 1) * 8;
    int acol_a = ((l >> 4) & 1) * 4;
    // B: lanes 0-7 rows,k0 | 8-15 rows,k4 | 16-23 rows+8,k0 | 24-31 rows+8,k4
    int arow_b = (l & 7) + ((l >> 4) & 1) * 8;
    int acol_b = ((l >> 3) & 1) * 4;
    unsigned aBase = smem_u32(As) + (unsigned)(((wm * 32 + arow_a) * 20 + acol_a) * 4);
    unsigned bBase = smem_u32(Bs) + (unsigned)(((wn * 64 + arow_b) * 20 + acol_b) * 4);

    int ar = tid >> 1, ak = (tid & 1) * 8;   // A fill: 2 float4 per thread
    int bnn = tid & 127, bk = (tid >> 7) * 8;
    const float* Ap = A + (size_t)(bm + ar) * Kd + ak;
    const float* Bp = Bm + bn + bnn;

    float4 a0v = *(const float4*)Ap;
    float4 a1v = *(const float4*)(Ap + 4);
    float btmp[8];
#pragma unroll
    for (int j = 0; j < 8; j++) btmp[j] = Bp[(size_t)(bk + j) * Nd];

    for (int k0 = 0; k0 < Kd; k0 += 16) {
        *(float4*)&As[ar * 20 + ak] =
            make_float4(tf32r(a0v.x), tf32r(a0v.y), tf32r(a0v.z), tf32r(a0v.w));
        *(float4*)&As[ar * 20 + ak + 4] =
            make_float4(tf32r(a1v.x), tf32r(a1v.y), tf32r(a1v.z), tf32r(a1v.w));
        *(float4*)&Bs[bnn * 20 + bk] =
            make_float4(tf32r(btmp[0]), tf32r(btmp[1]), tf32r(btmp[2]), tf32r(btmp[3]));
        *(float4*)&Bs[bnn * 20 + bk + 4] =
            make_float4(tf32r(btmp[4]), tf32r(btmp[5]), tf32r(btmp[6]), tf32r(btmp[7]));
        __syncthreads();
        if (k0 + 16 < Kd) {
            a0v = *(const float4*)(Ap + k0 + 16);
            a1v = *(const float4*)(Ap + k0 + 20);
#pragma unroll
            for (int j = 0; j < 8; j++) btmp[j] = Bp[(size_t)(k0 + 16 + bk + j) * Nd];
        }
#pragma unroll
        for (int ks = 0; ks < 2; ks++) {
            unsigned a0[4], a1[4];
            ldsm4(a0, aBase + ks * 32);
            ldsm4(a1, aBase + 16 * 80 + ks * 32);
#pragma unroll
            for (int ntp = 0; ntp < 4; ntp++) {
                unsigned bq[4];
                ldsm4(bq, bBase + ntp * 16 * 80 + ks * 32);
                mma8(acc[0][2 * ntp],     a0, bq);
                mma8(acc[1][2 * ntp],     a1, bq);
                mma8(acc[0][2 * ntp + 1], a0, bq + 2);
                mma8(acc[1][2 * ntp + 1], a1, bq + 2);
            }
        }
        __syncthreads();
    }
#pragma unroll
    for (int mt = 0; mt < 2; mt++) {
        int r0 = bm + wm * 32 + mt * 16 + lr;
#pragma unroll
        for (int nt = 0; nt < 8; nt++) {
            int c = bn + wn * 64 + nt * 8 + 2 * lc;
            float b0 = bias[c], b1 = bias[c + 1];
            *(float2*)&Cm[(size_t)r0 * Nd + c] =
                make_float2(acc[mt][nt][0] + b0, acc[mt][nt][1] + b1);
            *(float2*)&Cm[(size_t)(r0 + 8) * Nd + c] =
                make_float2(acc[mt][nt][2] + b0, acc[mt][nt][3] + b1);
        }
    }
}

// ---------------- 6. flash attention: R6 layout + ldmatrix fragment loads ----------------
__global__ __launch_bounds__(256, 2) void flash_tf32_k(
        const float* __restrict__ qkv, float* __restrict__ o) {
    extern __shared__ float sm[];
    float* Qs = sm;               // [128][68]  (m,k), pre-scaled by 0.125
    float* Ks = Qs + 128 * 68;    // [64][68]   K (n,k)
    float* Vs = Ks + 64 * 68;     // [64][68]   V^T (d,c)
    float* Ps = Vs + 64 * 68;     // [128][68]

    int qt = blockIdx.x, bh = blockIdx.y;
    int b = bh / HH, h = bh % HH;
    const float* base = qkv + (size_t)b * MM * C3 + h * 64;
    int tid = threadIdx.x;
    int w = tid >> 5, l = tid & 31;
    int lr = l >> 2, lc = l & 3;
    int mr0 = w * 16 + lr;

    int arow_a = (l & 7) + ((l >> 3) & 1) * 8;
    int acol_a = ((l >> 4) & 1) * 4;
    int arow_b = (l & 7) + ((l >> 4) & 1) * 8;
    int acol_b = ((l >> 3) & 1) * 4;
    unsigned qB = smem_u32(Qs) + (unsigned)(((w * 16 + arow_a) * 68 + acol_a) * 4);
    unsigned pB = smem_u32(Ps) + (unsigned)(((w * 16 + arow_a) * 68 + acol_a) * 4);
    unsigned kB = smem_u32(Ks) + (unsigned)((arow_b * 68 + acol_b) * 4);
    unsigned vB = smem_u32(Vs) + (unsigned)((arow_b * 68 + acol_b) * 4);

    {   // load Q once, fold in softmax scale (exact: *2^-3)
        int r = tid >> 1, hf = (tid & 1) * 32;
        const float* qp = base + (size_t)(qt * 128 + r) * C3 + hf;
#pragma unroll
        for (int i = 0; i < 8; i++) {
            float4 v = *(const float4*)(qp + i * 4);
            *(float4*)&Qs[r * 68 + hf + i * 4] =
                make_float4(tf32r(v.x * 0.125f), tf32r(v.y * 0.125f),
                            tf32r(v.z * 0.125f), tf32r(v.w * 0.125f));
        }
    }
    float om[8][4] = {};
    float m0 = -INFINITY, m1 = -INFINITY, l0 = 0.f, l1 = 0.f;

    for (int kt = 0; kt < 24; kt++) {
        __syncthreads();
        {   // load K tile (n,k)
            int r = tid >> 2, qq = (tid & 3) * 16;
            const float* kp = base + CC + (size_t)(kt * 64 + r) * C3 + qq;
#pragma unroll
            for (int i = 0; i < 4; i++) {
                float4 v = *(const float4*)(kp + i * 4);
                *(float4*)&Ks[r * 68 + qq + i * 4] =
                    make_float4(tf32r(v.x), tf32r(v.y), tf32r(v.z), tf32r(v.w));
            }
        }
        {   // load V transposed: Vt[d][c]
            int d = tid & 63, cb = (tid >> 6) * 16;
            const float* vp = base + 2 * CC + (size_t)(kt * 64 + cb) * C3 + d;
#pragma unroll
            for (int i = 0; i < 16; i++)
                Vs[d * 68 + cb + i] = tf32r(vp[(size_t)i * C3]);
        }
        __syncthreads();
        // S = Q K^T (already scaled)
        float s[8][4] = {};
#pragma unroll
        for (int ks = 0; ks < 8; ks++) {
            unsigned af[4];
            ldsm4(af, qB + ks * 32);
#pragma unroll
            for (int ntp = 0; ntp < 4; ntp++) {
                unsigned bq[4];
                ldsm4(bq, kB + ntp * 16 * 272 + ks * 32);
                mma8(s[2 * ntp],     af, bq);
                mma8(s[2 * ntp + 1], af, bq + 2);
            }
        }
        // online softmax
        float mx0 = -INFINITY, mx1 = -INFINITY;
#pragma unroll
        for (int nt = 0; nt < 8; nt++) {
            mx0 = fmaxf(mx0, fmaxf(s[nt][0], s[nt][1]));
            mx1 = fmaxf(mx1, fmaxf(s[nt][2], s[nt][3]));
        }
        mx0 = fmaxf(mx0, __shfl_xor_sync(0xffffffffu, mx0, 1));
        mx0 = fmaxf(mx0, __shfl_xor_sync(0xffffffffu, mx0, 2));
        mx1 = fmaxf(mx1, __shfl_xor_sync(0xffffffffu, mx1, 1));
        mx1 = fmaxf(mx1, __shfl_xor_sync(0xffffffffu, mx1, 2));
        float mn0 = fmaxf(m0, mx0), mn1 = fmaxf(m1, mx1);
        float al0 = __expf(m0 - mn0), al1 = __expf(m1 - mn1);
        m0 = mn0; m1 = mn1;
        float rs0 = 0.f, rs1 = 0.f;
#pragma unroll
        for (int nt = 0; nt < 8; nt++) {
            float p0 = __expf(s[nt][0] - mn0), p1 = __expf(s[nt][1] - mn0);
            float p2 = __expf(s[nt][2] - mn1), p3 = __expf(s[nt][3] - mn1);
            rs0 += p0 + p1; rs1 += p2 + p3;
            int c = nt * 8 + 2 * lc;
            *(float2*)&Ps[mr0 * 68 + c]       = make_float2(tf32r(p0), tf32r(p1));
            *(float2*)&Ps[(mr0 + 8) * 68 + c] = make_float2(tf32r(p2), tf32r(p3));
        }
        rs0 += __shfl_xor_sync(0xffffffffu, rs0, 1);
        rs0 += __shfl_xor_sync(0xffffffffu, rs0, 2);
        rs1 += __shfl_xor_sync(0xffffffffu, rs1, 1);
        rs1 += __shfl_xor_sync(0xffffffffu, rs1, 2);
        l0 = l0 * al0 + rs0; l1 = l1 * al1 + rs1;
#pragma unroll
        for (int nt = 0; nt < 8; nt++) {
            om[nt][0] *= al0; om[nt][1] *= al0;
            om[nt][2] *= al1; om[nt][3] *= al1;
        }
        __syncthreads();                    // Ps visible
        // O += P V
#pragma unroll
        for (int ks = 0; ks < 8; ks++) {
            unsigned af[4];
            ldsm4(af, pB + ks * 32);
#pragma unroll
            for (int ntp = 0; ntp < 4; ntp++) {
                unsigned bq[4];
                ldsm4(bq, vB + ntp * 16 * 272 + ks * 32);
                mma8(om[2 * ntp],     af, bq);
                mma8(om[2 * ntp + 1], af, bq + 2);
            }
        }
    }
    float i0 = 1.f / l0, i1 = 1.f / l1;
    size_t row0 = (size_t)b * MM + qt * 128 + mr0;
#pragma unroll
    for (int nt = 0; nt < 8; nt++) {
        int c = h * 64 + nt * 8 + 2 * lc;
        *(float2*)&o[row0 * CC + c]       = make_float2(om[nt][0] * i0, om[nt][1] * i0);
        *(float2*)&o[(row0 + 8) * CC + c] = make_float2(om[nt][2] * i1, om[nt][3] * i1);
    }
}

// ---------------- 7. unmerge ----------------
__global__ void unmerge_k(float* __restrict__ out) {
    int row = blockIdx.x;
    int b = row >> 11;
    int n = row & 2047;
    int yrow = (n & 1) ? (n >> 1) : g_gather[b * NSRC + (n >> 1)];
    const float* src = g_y + ((size_t)b * MM + yrow) * CC;
    float* dst = out + (size_t)row * CC;
    int t = threadIdx.x;                  // 192
    *(float4*)&dst[t * 4] = *(const float4*)&src[t * 4];
}

// ---------------- launcher ----------------
extern "C" void kernel_launch(void* const* d_in, const int* in_sizes, int n_in,
                              void* d_out, int out_size) {
    const float* x    = (const float*)d_in[0];
    const float* Wqkv = (const float*)d_in[1];
    const float* bqkv = (const float*)d_in[2];
    const float* Wo   = (const float*)d_in[3];
    const float* bo   = (const float*)d_in[4];
    float* out = (float*)d_out;

    float *xm, *qkvb, *attnb, *yb;
    cudaGetSymbolAddress((void**)&xm, g_xm);
    cudaGetSymbolAddress((void**)&qkvb, g_qkv);
    cudaGetSymbolAddress((void**)&attnb, g_attn);
    cudaGetSymbolAddress((void**)&yb, g_y);

    cudaFuncSetAttribute(flash_tf32_k, cudaFuncAttributeMaxDynamicSharedMemorySize, 104448);

    metric_k<<<BB * NN, 256>>>(x);
    match128_k<<<dim3(8, 8, 8), 256>>>();
    topk_k<<<BB, 1024>>>();
    buildall_k<<<BB * MM, 192>>>(x);
    gemm_tf32_k<<<dim3(C3 / 128, (BB * MM) / 128), 256>>>(xm, Wqkv, bqkv, qkvb, C3, CC);
    flash_tf32_k<<<dim3(MM / 128, BB * HH), 256, 104448>>>(qkvb, attnb);
    gemm_tf32_k<<<dim3(CC / 128, (BB * MM) / 128), 256>>>(attnb, Wo, bo, yb, CC, CC);
    unmerge_k<<<BB * NN, 192>>>(out);
}

// round 8
// speedup vs baseline: 1.3368x; 1.0348x over previous
#include <cuda_runtime.h>
#include <math.h>

#define BB 8
#define NN 2048
#define CC 768
#define HH 12
#define MM 1536
#define RR 512
#define NSRC 1024
#define NDST 1024
#define C3 2304

__device__ __forceinline__ float tf32r(float x) {
    unsigned r; asm("cvt.rna.tf32.f32 %0, %1;" : "=r"(r) : "f"(x));
    return __uint_as_float(r);
}
__device__ __forceinline__ void mma8(float c[4], const unsigned a[4], const unsigned b[2]) {
    asm volatile("mma.sync.aligned.m16n8k8.row.col.f32.tf32.tf32.f32 "
        "{%0,%1,%2,%3}, {%4,%5,%6,%7}, {%8,%9}, {%0,%1,%2,%3};"
        : "+f"(c[0]), "+f"(c[1]), "+f"(c[2]), "+f"(c[3])
        : "r"(a[0]), "r"(a[1]), "r"(a[2]), "r"(a[3]), "r"(b[0]), "r"(b[1]));
}
__device__ __forceinline__ void ldsm4(unsigned r[4], unsigned addr) {
    asm volatile("ldmatrix.sync.aligned.m8n8.x4.shared.b16 {%0,%1,%2,%3}, [%4];"
        : "=r"(r[0]), "=r"(r[1]), "=r"(r[2]), "=r"(r[3]) : "r"(addr));
}
__device__ __forceinline__ unsigned smem_u32(const void* p) {
    return (unsigned)__cvta_generic_to_shared(p);
}
__device__ __forceinline__ void cp16(unsigned d, const void* s) {
    asm volatile("cp.async.cg.shared.global [%0], [%1], 16;" :: "r"(d), "l"(s));
}
__device__ __forceinline__ void cp4(unsigned d, const void* s) {
    asm volatile("cp.async.ca.shared.global [%0], [%1], 4;" :: "r"(d), "l"(s));
}
__device__ __forceinline__ void cpcommit() { asm volatile("cp.async.commit_group;"); }
__device__ __forceinline__ void cpwait0()  { asm volatile("cp.async.wait_group 0;"); }

// ---------------- scratch ----------------
__device__ float g_mhi[(size_t)BB * NN * CC];
__device__ float g_mlo[(size_t)BB * NN * CC];
__device__ float g_pmax[BB * 8 * NSRC];
__device__ int   g_pidx[BB * 8 * NSRC];
__device__ int   g_srcidx[BB * RR];
__device__ int   g_unmidx[BB * RR];
__device__ int   g_gather[BB * NSRC];
__device__ int   g_lhead[BB * NSRC];
__device__ int   g_lnext[BB * RR];
__device__ float g_xm[(size_t)BB * MM * CC];
__device__ float g_qkv[(size_t)BB * MM * C3];
__device__ float g_attn[(size_t)BB * MM * CC];
__device__ float g_y[(size_t)BB * MM * CC];
__device__ float g_wqkv[CC * C3];
__device__ float g_wo[CC * CC];

// ---------------- 0. pre-round weights to tf32 ----------------
__global__ void roundcp_k(const float* __restrict__ s, float* __restrict__ d, int n) {
    int i = blockIdx.x * 256 + threadIdx.x;
    if (i < n) d[i] = tf32r(s[i]);
}

// ---------------- 1. normalized metric -> tf32 hi/lo split ----------------
__global__ void metric_k(const float* __restrict__ x) {
    int row = blockIdx.x;
    int tid = threadIdx.x;                 // 256
    const float* p = x + (size_t)row * CC;
    float v0 = p[tid], v1 = p[tid + 256], v2 = p[tid + 512];
    float s = v0 * v0 + v1 * v1 + v2 * v2;
    __shared__ float red[256];
    red[tid] = s; __syncthreads();
    for (int o = 128; o > 0; o >>= 1) {
        if (tid < o) red[tid] += red[tid + o];
        __syncthreads();
    }
    float nrm = sqrtf(red[0]);
    float m0 = v0 / nrm, m1 = v1 / nrm, m2 = v2 / nrm;
    float h0 = tf32r(m0), h1 = tf32r(m1), h2 = tf32r(m2);
    size_t off = (size_t)row * CC;
    g_mhi[off + tid] = h0;       g_mlo[off + tid] = tf32r(m0 - h0);
    g_mhi[off + tid + 256] = h1; g_mlo[off + tid + 256] = tf32r(m1 - h1);
    g_mhi[off + tid + 512] = h2; g_mlo[off + tid + 512] = tf32r(m2 - h2);
}

// ---------------- 2. matching scores via 3xTF32 MMA + fragment argmax ----------------
__global__ __launch_bounds__(256, 2) void match_mma_k() {
    extern __shared__ float dsm[];
    float* AH = dsm;               // [2][2560]
    float* AL = dsm + 5120;
    float* BH = dsm + 10240;
    float* BL = dsm + 15360;
    int dt = blockIdx.x, st = blockIdx.y, b = blockIdx.z;
    int tid = threadIdx.x;
    int w = tid >> 5, l = tid & 31;
    int wm = w & 3, wn = w >> 2;
    int lr = l >> 2, lc = l & 3;

    const float* mh = g_mhi + (size_t)b * NN * CC;
    const float* ml = g_mlo + (size_t)b * NN * CC;
    int ar = tid >> 1, ak = (tid & 1) * 8;
    size_t aoff = (size_t)(2 * (st * 128 + ar)) * CC + ak;
    size_t boff = (size_t)(2 * (dt * 128 + ar) + 1) * CC + ak;

    int arow_a = (l & 7) + ((l >> 3) & 1) * 8;
    int acol_a = ((l >> 4) & 1) * 4;
    int arow_b = (l & 7) + ((l >> 4) & 1) * 8;
    int acol_b = ((l >> 3) & 1) * 4;
    unsigned ahB = smem_u32(AH) + (unsigned)(((wm * 32 + arow_a) * 20 + acol_a) * 4);
    unsigned alB = smem_u32(AL) + (unsigned)(((wm * 32 + arow_a) * 20 + acol_a) * 4);
    unsigned bhB = smem_u32(BH) + (unsigned)(((wn * 64 + arow_b) * 20 + acol_b) * 4);
    unsigned blB = smem_u32(BL) + (unsigned)(((wn * 64 + arow_b) * 20 + acol_b) * 4);
    unsigned dsto = (unsigned)((ar * 20 + ak) * 4);

    float acc[2][8][4] = {};

    auto issue = [&](int c, int buf) {
        unsigned d = dsto + buf * 10240u;
        const float* a = mh + aoff + c * 16;
        const float* a2 = ml + aoff + c * 16;
        const float* bb = mh + boff + c * 16;
        const float* b2 = ml + boff + c * 16;
        cp16(smem_u32(AH) + d, a);       cp16(smem_u32(AH) + d + 16, a + 4);
        cp16(smem_u32(AL) + d, a2);      cp16(smem_u32(AL) + d + 16, a2 + 4);
        cp16(smem_u32(BH) + d, bb);      cp16(smem_u32(BH) + d + 16, bb + 4);
        cp16(smem_u32(BL) + d, b2);      cp16(smem_u32(BL) + d + 16, b2 + 4);
    };

    issue(0, 0); cpcommit();
    int buf = 0;
    for (int c = 0; c < 48; c++) {
        cpwait0();
        __syncthreads();
        if (c + 1 < 48) { issue(c + 1, buf ^ 1); cpcommit(); }
        unsigned bo = (unsigned)(buf * 10240);
#pragma unroll
        for (int ks = 0; ks < 2; ks++) {
            unsigned o = bo + ks * 32;
            unsigned a0h[4], a1h[4], a0l[4], a1l[4];
            ldsm4(a0h, ahB + o); ldsm4(a1h, ahB + 16 * 80 + o);
            ldsm4(a0l, alB + o); ldsm4(a1l, alB + 16 * 80 + o);
#pragma unroll
            for (int ntp = 0; ntp < 4; ntp++) {
                unsigned bh4[4], bl4[4];
                ldsm4(bh4, bhB + ntp * 16 * 80 + o);
                ldsm4(bl4, blB + ntp * 16 * 80 + o);
                mma8(acc[0][2 * ntp],     a0h, bh4);
                mma8(acc[1][2 * ntp],     a1h, bh4);
                mma8(acc[0][2 * ntp + 1], a0h, bh4 + 2);
                mma8(acc[1][2 * ntp + 1], a1h, bh4 + 2);
                mma8(acc[0][2 * ntp],     a0h, bl4);
                mma8(acc[1][2 * ntp],     a1h, bl4);
                mma8(acc[0][2 * ntp + 1], a0h, bl4 + 2);
                mma8(acc[1][2 * ntp + 1], a1h, bl4 + 2);
                mma8(acc[0][2 * ntp],     a0l, bh4);
                mma8(acc[1][2 * ntp],     a1l, bh4);
                mma8(acc[0][2 * ntp + 1], a0l, bh4 + 2);
                mma8(acc[1][2 * ntp + 1], a1l, bh4 + 2);
            }
        }
        buf ^= 1;
    }
    // fragment argmax epilogue (first-occurrence ties)
    float* spm = dsm;                 // [2][128]
    int*   spi = (int*)(dsm + 256);   // [2][128]
    __syncthreads();
#pragma unroll
    for (int mt = 0; mt < 2; mt++) {
        float bv0 = -INFINITY, bv1 = -INFINITY;
        int bi0 = 0, bi1 = 0;
#pragma unroll
        for (int nt = 0; nt < 8; nt++) {
            int cb = dt * 128 + wn * 64 + nt * 8 + 2 * lc;
            if (acc[mt][nt][0] > bv0) { bv0 = acc[mt][nt][0]; bi0 = cb; }
            if (acc[mt][nt][1] > bv0) { bv0 = acc[mt][nt][1]; bi0 = cb + 1; }
            if (acc[mt][nt][2] > bv1) { bv1 = acc[mt][nt][2]; bi1 = cb; }
            if (acc[mt][nt][3] > bv1) { bv1 = acc[mt][nt][3]; bi1 = cb + 1; }
        }
#pragma unroll
        for (int off = 1; off <= 2; off <<= 1) {
            float ov = __shfl_xor_sync(0xffffffffu, bv0, off);
            int   oi = __shfl_xor_sync(0xffffffffu, bi0, off);
            if (ov > bv0 || (ov == bv0 && oi < bi0)) { bv0 = ov; bi0 = oi; }
            ov = __shfl_xor_sync(0xffffffffu, bv1, off);
            oi = __shfl_xor_sync(0xffffffffu, bi1, off);
            if (ov > bv1 || (ov == bv1 && oi < bi1)) { bv1 = ov; bi1 = oi; }
        }
        if (lc == 0) {
            int r0 = wm * 32 + mt * 16 + lr;
            spm[wn * 128 + r0] = bv0;  spi[wn * 128 + r0] = bi0;
            spm[wn * 128 + r0 + 8] = bv1; spi[wn * 128 + r0 + 8] = bi1;
        }
    }
    __syncthreads();
    if (tid < 128) {
        float v0 = spm[tid], v1 = spm[128 + tid];
        int   i0 = spi[tid], i1 = spi[128 + tid];
        if (v1 > v0) { v0 = v1; i0 = i1; }    // wn1 indices always larger: tie keeps wn0
        g_pmax[(b * 8 + dt) * NSRC + st * 128 + tid] = v0;
        g_pidx[(b * 8 + dt) * NSRC + st * 128 + tid] = i0;
    }
}

// ---------------- 3. top-k (fused partial-reduce + bitonic + lists) ----------------
__global__ void topk_k() {
    __shared__ unsigned long long key[1024];
    __shared__ int nidx[1024];
    __shared__ int mrg[1024];
    __shared__ int scn[1024];
    int b = blockIdx.x, tid = threadIdx.x;   // 1024

    float bv = g_pmax[(b * 8) * NSRC + tid];
    int   bi = g_pidx[(b * 8) * NSRC + tid];
#pragma unroll
    for (int dt = 1; dt < 8; dt++) {
        float v = g_pmax[(b * 8 + dt) * NSRC + tid];
        if (v > bv) { bv = v; bi = g_pidx[(b * 8 + dt) * NSRC + tid]; }
    }
    nidx[tid] = bi;
    {
        unsigned u = __float_as_uint(bv);
        u = (u & 0x80000000u) ? ~u : (u | 0x80000000u);
        key[tid] = ((unsigned long long)(~u) << 32) | (unsigned)tid;
    }
    mrg[tid] = 0;
    g_lhead[b * NSRC + tid] = -1;
    __syncthreads();
    for (int k = 2; k <= 1024; k <<= 1)
        for (int j = k >> 1; j > 0; j >>= 1) {
            int p = tid ^ j;
            if (p > tid) {
                bool up = ((tid & k) == 0);
                unsigned long long a = key[tid], c2 = key[p];
                if ((a > c2) == up) { key[tid] = c2; key[p] = a; }
            }
            __syncthreads();
        }
    if (tid < 512) {
        int s = (int)(key[tid] & 0xffffffffu);
        g_srcidx[b * RR + tid] = s;
        mrg[s] = 1;
        int d = nidx[s];
        g_lnext[b * RR + tid] = atomicExch(&g_lhead[b * NSRC + d], tid);
    }
    __syncthreads();
    int um = mrg[tid] ? 0 : 1;
    scn[tid] = um; __syncthreads();
    for (int off = 1; off < 1024; off <<= 1) {
        int v = scn[tid];
        int v2 = (tid >= off) ? scn[tid - off] : 0;
        __syncthreads();
        scn[tid] = v + v2; __syncthreads();
    }
    int rnk = scn[tid] - um;
    if (um) { g_unmidx[b * RR + rnk] = tid; g_gather[b * NSRC + tid] = NDST + rnk; }
    else    { g_gather[b * NSRC + tid] = nidx[tid]; }
}

// ---------------- 4. fused merge build (now emits tf32-rounded xm) ----------------
__global__ void buildall_k(const float* __restrict__ x) {
    int row = blockIdx.x;                   // 0..B*MM-1
    int b = row / MM, j = row - b * MM;
    int t = threadIdx.x;                    // 192
    float* dst = g_xm + (size_t)row * CC;
    if (j >= NDST) {
        int s = g_unmidx[b * RR + (j - NDST)];
        const float* src = x + ((size_t)b * NN + 2 * s) * CC;
        float4 v = *(const float4*)&src[t * 4];
        *(float4*)&dst[t * 4] =
            make_float4(tf32r(v.x), tf32r(v.y), tf32r(v.z), tf32r(v.w));
        return;
    }
    const float* dsrc = x + ((size_t)b * NN + 2 * j + 1) * CC;
    float4 v = *(const float4*)&dsrc[t * 4];
    float cntf = 1.f;
    int it = g_lhead[b * NSRC + j];
    while (it >= 0) {
        int s = g_srcidx[b * RR + it];
        float4 sv = *(const float4*)&x[((size_t)b * NN + 2 * s) * CC + t * 4];
        v.x += sv.x; v.y += sv.y; v.z += sv.z; v.w += sv.w;
        cntf += 1.f;
        it = g_lnext[b * RR + it];
    }
    float inv = 1.f / cntf;
    *(float4*)&dst[t * 4] =
        make_float4(tf32r(v.x * inv), tf32r(v.y * inv), tf32r(v.z * inv), tf32r(v.w * inv));
}

// ---------------- 5. tf32 GEMM: cp.async double-buffered, pre-rounded inputs ----------------
__global__ __launch_bounds__(256, 2) void gemm_tf32_k(
        const float* __restrict__ A, const float* __restrict__ Bm,
        const float* __restrict__ bias, float* __restrict__ Cm, int Nd, int Kd) {
    __shared__ float As[2][128 * 20];
    __shared__ float Bs[2][128 * 20];
    int tid = threadIdx.x;
    int w = tid >> 5, l = tid & 31;
    int wm = w & 3, wn = w >> 2;
    int lr = l >> 2, lc = l & 3;
    int bm = blockIdx.y * 128, bn = blockIdx.x * 128;
    float acc[2][8][4] = {};

    int arow_a = (l & 7) + ((l >> 3) & 1) * 8;
    int acol_a = ((l >> 4) & 1) * 4;
    int arow_b = (l & 7) + ((l >> 4) & 1) * 8;
    int acol_b = ((l >> 3) & 1) * 4;
    unsigned aBase = smem_u32(As) + (unsigned)(((wm * 32 + arow_a) * 20 + acol_a) * 4);
    unsigned bBase = smem_u32(Bs) + (unsigned)(((wn * 64 + arow_b) * 20 + acol_b) * 4);

    int ar = tid >> 1, ak = (tid & 1) * 8;
    int bnn = tid & 127, bk = (tid >> 7) * 8;
    const float* Ap = A + (size_t)(bm + ar) * Kd + ak;
    const float* Bp = Bm + bn + bnn;
    unsigned adst = smem_u32(As) + (unsigned)((ar * 20 + ak) * 4);
    unsigned bdst = smem_u32(Bs) + (unsigned)((bnn * 20 + bk) * 4);

    auto issue = [&](int c, int buf) {
        unsigned off = buf * 10240u;
        const float* a = Ap + c * 16;
        cp16(adst + off, a);
        cp16(adst + off + 16, a + 4);
#pragma unroll
        for (int i = 0; i < 8; i++)
            cp4(bdst + off + i * 4, Bp + (size_t)(c * 16 + bk + i) * Nd);
    };

    int nchunk = Kd >> 4;
    issue(0, 0); cpcommit();
    int buf = 0;
    for (int c = 0; c < nchunk; c++) {
        cpwait0();
        __syncthreads();
        if (c + 1 < nchunk) { issue(c + 1, buf ^ 1); cpcommit(); }
        unsigned bo = (unsigned)(buf * 10240);
#pragma unroll
        for (int ks = 0; ks < 2; ks++) {
            unsigned a0[4], a1[4];
            ldsm4(a0, aBase + bo + ks * 32);
            ldsm4(a1, aBase + bo + 16 * 80 + ks * 32);
#pragma unroll
            for (int ntp = 0; ntp < 4; ntp++) {
                unsigned bq[4];
                ldsm4(bq, bBase + bo + ntp * 16 * 80 + ks * 32);
                mma8(acc[0][2 * ntp],     a0, bq);
                mma8(acc[1][2 * ntp],     a1, bq);
                mma8(acc[0][2 * ntp + 1], a0, bq + 2);
                mma8(acc[1][2 * ntp + 1], a1, bq + 2);
            }
        }
        buf ^= 1;
    }
#pragma unroll
    for (int mt = 0; mt < 2; mt++) {
        int r0 = bm + wm * 32 + mt * 16 + lr;
#pragma unroll
        for (int nt = 0; nt < 8; nt++) {
            int c = bn + wn * 64 + nt * 8 + 2 * lc;
            float b0 = bias[c], b1 = bias[c + 1];
            *(float2*)&Cm[(size_t)r0 * Nd + c] =
                make_float2(acc[mt][nt][0] + b0, acc[mt][nt][1] + b1);
            *(float2*)&Cm[(size_t)(r0 + 8) * Nd + c] =
                make_float2(acc[mt][nt][2] + b0, acc[mt][nt][3] + b1);
        }
    }
}

// ---------------- 6. flash attention (R7-verified; output tf32-rounded) ----------------
__global__ __launch_bounds__(256, 2) void flash_tf32_k(
        const float* __restrict__ qkv, float* __restrict__ o) {
    extern __shared__ float sm[];
    float* Qs = sm;               // [128][68]  (m,k), pre-scaled by 0.125
    float* Ks = Qs + 128 * 68;    // [64][68]   K (n,k)
    float* Vs = Ks + 64 * 68;     // [64][68]   V^T (d,c)
    float* Ps = Vs + 64 * 68;     // [128][68]

    int qt = blockIdx.x, bh = blockIdx.y;
    int b = bh / HH, h = bh % HH;
    const float* base = qkv + (size_t)b * MM * C3 + h * 64;
    int tid = threadIdx.x;
    int w = tid >> 5, l = tid & 31;
    int lr = l >> 2, lc = l & 3;
    int mr0 = w * 16 + lr;

    int arow_a = (l & 7) + ((l >> 3) & 1) * 8;
    int acol_a = ((l >> 4) & 1) * 4;
    int arow_b = (l & 7) + ((l >> 4) & 1) * 8;
    int acol_b = ((l >> 3) & 1) * 4;
    unsigned qB = smem_u32(Qs) + (unsigned)(((w * 16 + arow_a) * 68 + acol_a) * 4);
    unsigned pB = smem_u32(Ps) + (unsigned)(((w * 16 + arow_a) * 68 + acol_a) * 4);
    unsigned kB = smem_u32(Ks) + (unsigned)((arow_b * 68 + acol_b) * 4);
    unsigned vB = smem_u32(Vs) + (unsigned)((arow_b * 68 + acol_b) * 4);

    {   // load Q once, fold in softmax scale (exact: *2^-3)
        int r = tid >> 1, hf = (tid & 1) * 32;
        const float* qp = base + (size_t)(qt * 128 + r) * C3 + hf;
#pragma unroll
        for (int i = 0; i < 8; i++) {
            float4 v = *(const float4*)(qp + i * 4);
            *(float4*)&Qs[r * 68 + hf + i * 4] =
                make_float4(tf32r(v.x * 0.125f), tf32r(v.y * 0.125f),
                            tf32r(v.z * 0.125f), tf32r(v.w * 0.125f));
        }
    }
    float om[8][4] = {};
    float m0 = -INFINITY, m1 = -INFINITY, l0 = 0.f, l1 = 0.f;

    for (int kt = 0; kt < 24; kt++) {
        __syncthreads();
        {   // load K tile (n,k)
            int r = tid >> 2, qq = (tid & 3) * 16;
            const float* kp = base + CC + (size_t)(kt * 64 + r) * C3 + qq;
#pragma unroll
            for (int i = 0; i < 4; i++) {
                float4 v = *(const float4*)(kp + i * 4);
                *(float4*)&Ks[r * 68 + qq + i * 4] =
                    make_float4(tf32r(v.x), tf32r(v.y), tf32r(v.z), tf32r(v.w));
            }
        }
        {   // load V transposed: Vt[d][c]
            int d = tid & 63, cb = (tid >> 6) * 16;
            const float* vp = base + 2 * CC + (size_t)(kt * 64 + cb) * C3 + d;
#pragma unroll
            for (int i = 0; i < 16; i++)
                Vs[d * 68 + cb + i] = tf32r(vp[(size_t)i * C3]);
        }
        __syncthreads();
        float s[8][4] = {};
#pragma unroll
        for (int ks = 0; ks < 8; ks++) {
            unsigned af[4];
            ldsm4(af, qB + ks * 32);
#pragma unroll
            for (int ntp = 0; ntp < 4; ntp++) {
                unsigned bq[4];
                ldsm4(bq, kB + ntp * 16 * 272 + ks * 32);
                mma8(s[2 * ntp],     af, bq);
                mma8(s[2 * ntp + 1], af, bq + 2);
            }
        }
        float mx0 = -INFINITY, mx1 = -INFINITY;
#pragma unroll
        for (int nt = 0; nt < 8; nt++) {
            mx0 = fmaxf(mx0, fmaxf(s[nt][0], s[nt][1]));
            mx1 = fmaxf(mx1, fmaxf(s[nt][2], s[nt][3]));
        }
        mx0 = fmaxf(mx0, __shfl_xor_sync(0xffffffffu, mx0, 1));
        mx0 = fmaxf(mx0, __shfl_xor_sync(0xffffffffu, mx0, 2));
        mx1 = fmaxf(mx1, __shfl_xor_sync(0xffffffffu, mx1, 1));
        mx1 = fmaxf(mx1, __shfl_xor_sync(0xffffffffu, mx1, 2));
        float mn0 = fmaxf(m0, mx0), mn1 = fmaxf(m1, mx1);
        float al0 = __expf(m0 - mn0), al1 = __expf(m1 - mn1);
        m0 = mn0; m1 = mn1;
        float rs0 = 0.f, rs1 = 0.f;
#pragma unroll
        for (int nt = 0; nt < 8; nt++) {
            float p0 = __expf(s[nt][0] - mn0), p1 = __expf(s[nt][1] - mn0);
            float p2 = __expf(s[nt][2] - mn1), p3 = __expf(s[nt][3] - mn1);
            rs0 += p0 + p1; rs1 += p2 + p3;
            int c = nt * 8 + 2 * lc;
            *(float2*)&Ps[mr0 * 68 + c]       = make_float2(tf32r(p0), tf32r(p1));
            *(float2*)&Ps[(mr0 + 8) * 68 + c] = make_float2(tf32r(p2), tf32r(p3));
        }
        rs0 += __shfl_xor_sync(0xffffffffu, rs0, 1);
        rs0 += __shfl_xor_sync(0xffffffffu, rs0, 2);
        rs1 += __shfl_xor_sync(0xffffffffu, rs1, 1);
        rs1 += __shfl_xor_sync(0xffffffffu, rs1, 2);
        l0 = l0 * al0 + rs0; l1 = l1 * al1 + rs1;
#pragma unroll
        for (int nt = 0; nt < 8; nt++) {
            om[nt][0] *= al0; om[nt][1] *= al0;
            om[nt][2] *= al1; om[nt][3] *= al1;
        }
        __syncthreads();
#pragma unroll
        for (int ks = 0; ks < 8; ks++) {
            unsigned af[4];
            ldsm4(af, pB + ks * 32);
#pragma unroll
            for (int ntp = 0; ntp < 4; ntp++) {
                unsigned bq[4];
                ldsm4(bq, vB + ntp * 16 * 272 + ks * 32);
                mma8(om[2 * ntp],     af, bq);
                mma8(om[2 * ntp + 1], af, bq + 2);
            }
        }
    }
    float i0 = 1.f / l0, i1 = 1.f / l1;
    size_t row0 = (size_t)b * MM + qt * 128 + mr0;
#pragma unroll
    for (int nt = 0; nt < 8; nt++) {
        int c = h * 64 + nt * 8 + 2 * lc;
        *(float2*)&o[row0 * CC + c] =
            make_float2(tf32r(om[nt][0] * i0), tf32r(om[nt][1] * i0));
        *(float2*)&o[(row0 + 8) * CC + c] =
            make_float2(tf32r(om[nt][2] * i1), tf32r(om[nt][3] * i1));
    }
}

// ---------------- 7. unmerge ----------------
__global__ void unmerge_k(float* __restrict__ out) {
    int row = blockIdx.x;
    int b = row >> 11;
    int n = row & 2047;
    int yrow = (n & 1) ? (n >> 1) : g_gather[b * NSRC + (n >> 1)];
    const float* src = g_y + ((size_t)b * MM + yrow) * CC;
    float* dst = out + (size_t)row * CC;
    int t = threadIdx.x;                  // 192
    *(float4*)&dst[t * 4] = *(const float4*)&src[t * 4];
}

// ---------------- launcher ----------------
extern "C" void kernel_launch(void* const* d_in, const int* in_sizes, int n_in,
                              void* d_out, int out_size) {
    const float* x    = (const float*)d_in[0];
    const float* Wqkv = (const float*)d_in[1];
    const float* bqkv = (const float*)d_in[2];
    const float* Wo   = (const float*)d_in[3];
    const float* bo   = (const float*)d_in[4];
    float* out = (float*)d_out;

    float *xm, *qkvb, *attnb, *yb, *wq, *wo;
    cudaGetSymbolAddress((void**)&xm, g_xm);
    cudaGetSymbolAddress((void**)&qkvb, g_qkv);
    cudaGetSymbolAddress((void**)&attnb, g_attn);
    cudaGetSymbolAddress((void**)&yb, g_y);
    cudaGetSymbolAddress((void**)&wq, g_wqkv);
    cudaGetSymbolAddress((void**)&wo, g_wo);

    cudaFuncSetAttribute(flash_tf32_k, cudaFuncAttributeMaxDynamicSharedMemorySize, 104448);
    cudaFuncSetAttribute(match_mma_k, cudaFuncAttributeMaxDynamicSharedMemorySize, 81920);

    roundcp_k<<<(CC * C3 + 255) / 256, 256>>>(Wqkv, wq, CC * C3);
    roundcp_k<<<(CC * CC + 255) / 256, 256>>>(Wo, wo, CC * CC);
    metric_k<<<BB * NN, 256>>>(x);
    match_mma_k<<<dim3(8, 8, 8), 256, 81920>>>();
    topk_k<<<BB, 1024>>>();
    buildall_k<<<BB * MM, 192>>>(x);
    gemm_tf32_k<<<dim3(C3 / 128, (BB * MM) / 128), 256>>>(xm, wq, bqkv, qkvb, C3, CC);
    flash_tf32_k<<<dim3(MM / 128, BB * HH), 256, 104448>>>(qkvb, attnb);
    gemm_tf32_k<<<dim3(CC / 128, (BB * MM) / 128), 256>>>(attnb, wo, bo, yb, CC, CC);
    unmerge_k<<<BB * NN, 192>>>(out);
}

// round 9
// speedup vs baseline: 1.4467x; 1.0822x over previous
#include <cuda_runtime.h>
#include <math.h>

#define BB 8
#define NN 2048
#define CC 768
#define HH 12
#define MM 1536
#define RR 512
#define NSRC 1024
#define NDST 1024
#define C3 2304

__device__ __forceinline__ float tf32r(float x) {
    unsigned r; asm("cvt.rna.tf32.f32 %0, %1;" : "=r"(r) : "f"(x));
    return __uint_as_float(r);
}
__device__ __forceinline__ void mma8(float c[4], const unsigned a[4], const unsigned b[2]) {
    asm volatile("mma.sync.aligned.m16n8k8.row.col.f32.tf32.tf32.f32 "
        "{%0,%1,%2,%3}, {%4,%5,%6,%7}, {%8,%9}, {%0,%1,%2,%3};"
        : "+f"(c[0]), "+f"(c[1]), "+f"(c[2]), "+f"(c[3])
        : "r"(a[0]), "r"(a[1]), "r"(a[2]), "r"(a[3]), "r"(b[0]), "r"(b[1]));
}
__device__ __forceinline__ void ldsm4(unsigned r[4], unsigned addr) {
    asm volatile("ldmatrix.sync.aligned.m8n8.x4.shared.b16 {%0,%1,%2,%3}, [%4];"
        : "=r"(r[0]), "=r"(r[1]), "=r"(r[2]), "=r"(r[3]) : "r"(addr));
}
__device__ __forceinline__ unsigned smem_u32(const void* p) {
    return (unsigned)__cvta_generic_to_shared(p);
}
__device__ __forceinline__ void cp16(unsigned d, const void* s) {
    asm volatile("cp.async.cg.shared.global [%0], [%1], 16;" :: "r"(d), "l"(s));
}
__device__ __forceinline__ void cp4(unsigned d, const void* s) {
    asm volatile("cp.async.ca.shared.global [%0], [%1], 4;" :: "r"(d), "l"(s));
}
__device__ __forceinline__ void cpcommit() { asm volatile("cp.async.commit_group;"); }
__device__ __forceinline__ void cpwait0()  { asm volatile("cp.async.wait_group 0;"); }

#define U(x) __float_as_uint(x)

// ---------------- scratch ----------------
__device__ float g_mhi[(size_t)BB * NN * CC];
__device__ float g_mlo[(size_t)BB * NN * CC];
__device__ float g_pmax[BB * 8 * NSRC];
__device__ int   g_pidx[BB * 8 * NSRC];
__device__ int   g_srcidx[BB * RR];
__device__ int   g_unmidx[BB * RR];
__device__ int   g_gather[BB * NSRC];
__device__ int   g_lhead[BB * NSRC];
__device__ int   g_lnext[BB * RR];
__device__ float g_xm[(size_t)BB * MM * CC];
__device__ float g_qkv[(size_t)BB * MM * C3];
__device__ float g_attn[(size_t)BB * MM * CC];
__device__ float g_y[(size_t)BB * MM * CC];
__device__ float g_wqkv[CC * C3];
__device__ float g_wo[CC * CC];

// ---------------- 0. pre-round weights to tf32 ----------------
__global__ void roundcp_k(const float* __restrict__ s, float* __restrict__ d, int n) {
    int i = blockIdx.x * 256 + threadIdx.x;
    if (i < n) d[i] = tf32r(s[i]);
}

// ---------------- 1. normalized metric -> tf32 hi/lo split ----------------
__global__ void metric_k(const float* __restrict__ x) {
    int row = blockIdx.x;
    int tid = threadIdx.x;                 // 256
    const float* p = x + (size_t)row * CC;
    float v0 = p[tid], v1 = p[tid + 256], v2 = p[tid + 512];
    float s = v0 * v0 + v1 * v1 + v2 * v2;
    __shared__ float red[256];
    red[tid] = s; __syncthreads();
    for (int o = 128; o > 0; o >>= 1) {
        if (tid < o) red[tid] += red[tid + o];
        __syncthreads();
    }
    float nrm = sqrtf(red[0]);
    float m0 = v0 / nrm, m1 = v1 / nrm, m2 = v2 / nrm;
    float h0 = tf32r(m0), h1 = tf32r(m1), h2 = tf32r(m2);
    size_t off = (size_t)row * CC;
    g_mhi[off + tid] = h0;       g_mlo[off + tid] = tf32r(m0 - h0);
    g_mhi[off + tid + 256] = h1; g_mlo[off + tid + 256] = tf32r(m1 - h1);
    g_mhi[off + tid + 512] = h2; g_mlo[off + tid + 512] = tf32r(m2 - h2);
}

// ---------------- 2. matching scores via 3xTF32 MMA + fragment argmax (R8-verified) ----------------
__global__ __launch_bounds__(256, 2) void match_mma_k() {
    extern __shared__ float dsm[];
    float* AH = dsm;               // [2][2560]
    float* AL = dsm + 5120;
    float* BH = dsm + 10240;
    float* BL = dsm + 15360;
    int dt = blockIdx.x, st = blockIdx.y, b = blockIdx.z;
    int tid = threadIdx.x;
    int w = tid >> 5, l = tid & 31;
    int wm = w & 3, wn = w >> 2;
    int lr = l >> 2, lc = l & 3;

    const float* mh = g_mhi + (size_t)b * NN * CC;
    const float* ml = g_mlo + (size_t)b * NN * CC;
    int ar = tid >> 1, ak = (tid & 1) * 8;
    size_t aoff = (size_t)(2 * (st * 128 + ar)) * CC + ak;
    size_t boff = (size_t)(2 * (dt * 128 + ar) + 1) * CC + ak;

    int arow_a = (l & 7) + ((l >> 3) & 1) * 8;
    int acol_a = ((l >> 4) & 1) * 4;
    int arow_b = (l & 7) + ((l >> 4) & 1) * 8;
    int acol_b = ((l >> 3) & 1) * 4;
    unsigned ahB = smem_u32(AH) + (unsigned)(((wm * 32 + arow_a) * 20 + acol_a) * 4);
    unsigned alB = smem_u32(AL) + (unsigned)(((wm * 32 + arow_a) * 20 + acol_a) * 4);
    unsigned bhB = smem_u32(BH) + (unsigned)(((wn * 64 + arow_b) * 20 + acol_b) * 4);
    unsigned blB = smem_u32(BL) + (unsigned)(((wn * 64 + arow_b) * 20 + acol_b) * 4);
    unsigned dsto = (unsigned)((ar * 20 + ak) * 4);

    float acc[2][8][4] = {};

    auto issue = [&](int c, int buf) {
        unsigned d = dsto + buf * 10240u;
        const float* a = mh + aoff + c * 16;
        const float* a2 = ml + aoff + c * 16;
        const float* bb = mh + boff + c * 16;
        const float* b2 = ml + boff + c * 16;
        cp16(smem_u32(AH) + d, a);       cp16(smem_u32(AH) + d + 16, a + 4);
        cp16(smem_u32(AL) + d, a2);      cp16(smem_u32(AL) + d + 16, a2 + 4);
        cp16(smem_u32(BH) + d, bb);      cp16(smem_u32(BH) + d + 16, bb + 4);
        cp16(smem_u32(BL) + d, b2);      cp16(smem_u32(BL) + d + 16, b2 + 4);
    };

    issue(0, 0); cpcommit();
    int buf = 0;
    for (int c = 0; c < 48; c++) {
        cpwait0();
        __syncthreads();
        if (c + 1 < 48) { issue(c + 1, buf ^ 1); cpcommit(); }
        unsigned bo = (unsigned)(buf * 10240);
#pragma unroll
        for (int ks = 0; ks < 2; ks++) {
            unsigned o = bo + ks * 32;
            unsigned a0h[4], a1h[4], a0l[4], a1l[4];
            ldsm4(a0h, ahB + o); ldsm4(a1h, ahB + 16 * 80 + o);
            ldsm4(a0l, alB + o); ldsm4(a1l, alB + 16 * 80 + o);
#pragma unroll
            for (int ntp = 0; ntp < 4; ntp++) {
                unsigned bh4[4], bl4[4];
                ldsm4(bh4, bhB + ntp * 16 * 80 + o);
                ldsm4(bl4, blB + ntp * 16 * 80 + o);
                mma8(acc[0][2 * ntp],     a0h, bh4);
                mma8(acc[1][2 * ntp],     a1h, bh4);
                mma8(acc[0][2 * ntp + 1], a0h, bh4 + 2);
                mma8(acc[1][2 * ntp + 1], a1h, bh4 + 2);
                mma8(acc[0][2 * ntp],     a0h, bl4);
                mma8(acc[1][2 * ntp],     a1h, bl4);
                mma8(acc[0][2 * ntp + 1], a0h, bl4 + 2);
                mma8(acc[1][2 * ntp + 1], a1h, bl4 + 2);
                mma8(acc[0][2 * ntp],     a0l, bh4);
                mma8(acc[1][2 * ntp],     a1l, bh4);
                mma8(acc[0][2 * ntp + 1], a0l, bh4 + 2);
                mma8(acc[1][2 * ntp + 1], a1l, bh4 + 2);
            }
        }
        buf ^= 1;
    }
    float* spm = dsm;
    int*   spi = (int*)(dsm + 256);
    __syncthreads();
#pragma unroll
    for (int mt = 0; mt < 2; mt++) {
        float bv0 = -INFINITY, bv1 = -INFINITY;
        int bi0 = 0, bi1 = 0;
#pragma unroll
        for (int nt = 0; nt < 8; nt++) {
            int cb = dt * 128 + wn * 64 + nt * 8 + 2 * lc;
            if (acc[mt][nt][0] > bv0) { bv0 = acc[mt][nt][0]; bi0 = cb; }
            if (acc[mt][nt][1] > bv0) { bv0 = acc[mt][nt][1]; bi0 = cb + 1; }
            if (acc[mt][nt][2] > bv1) { bv1 = acc[mt][nt][2]; bi1 = cb; }
            if (acc[mt][nt][3] > bv1) { bv1 = acc[mt][nt][3]; bi1 = cb + 1; }
        }
#pragma unroll
        for (int off = 1; off <= 2; off <<= 1) {
            float ov = __shfl_xor_sync(0xffffffffu, bv0, off);
            int   oi = __shfl_xor_sync(0xffffffffu, bi0, off);
            if (ov > bv0 || (ov == bv0 && oi < bi0)) { bv0 = ov; bi0 = oi; }
            ov = __shfl_xor_sync(0xffffffffu, bv1, off);
            oi = __shfl_xor_sync(0xffffffffu, bi1, off);
            if (ov > bv1 || (ov == bv1 && oi < bi1)) { bv1 = ov; bi1 = oi; }
        }
        if (lc == 0) {
            int r0 = wm * 32 + mt * 16 + lr;
            spm[wn * 128 + r0] = bv0;  spi[wn * 128 + r0] = bi0;
            spm[wn * 128 + r0 + 8] = bv1; spi[wn * 128 + r0 + 8] = bi1;
        }
    }
    __syncthreads();
    if (tid < 128) {
        float v0 = spm[tid], v1 = spm[128 + tid];
        int   i0 = spi[tid], i1 = spi[128 + tid];
        if (v1 > v0) { v0 = v1; i0 = i1; }
        g_pmax[(b * 8 + dt) * NSRC + st * 128 + tid] = v0;
        g_pidx[(b * 8 + dt) * NSRC + st * 128 + tid] = i0;
    }
}

// ---------------- 3. top-k (R8-verified) ----------------
__global__ void topk_k() {
    __shared__ unsigned long long key[1024];
    __shared__ int nidx[1024];
    __shared__ int mrg[1024];
    __shared__ int scn[1024];
    int b = blockIdx.x, tid = threadIdx.x;   // 1024

    float bv = g_pmax[(b * 8) * NSRC + tid];
    int   bi = g_pidx[(b * 8) * NSRC + tid];
#pragma unroll
    for (int dt = 1; dt < 8; dt++) {
        float v = g_pmax[(b * 8 + dt) * NSRC + tid];
        if (v > bv) { bv = v; bi = g_pidx[(b * 8 + dt) * NSRC + tid]; }
    }
    nidx[tid] = bi;
    {
        unsigned u = __float_as_uint(bv);
        u = (u & 0x80000000u) ? ~u : (u | 0x80000000u);
        key[tid] = ((unsigned long long)(~u) << 32) | (unsigned)tid;
    }
    mrg[tid] = 0;
    g_lhead[b * NSRC + tid] = -1;
    __syncthreads();
    for (int k = 2; k <= 1024; k <<= 1)
        for (int j = k >> 1; j > 0; j >>= 1) {
            int p = tid ^ j;
            if (p > tid) {
                bool up = ((tid & k) == 0);
                unsigned long long a = key[tid], c2 = key[p];
                if ((a > c2) == up) { key[tid] = c2; key[p] = a; }
            }
            __syncthreads();
        }
    if (tid < 512) {
        int s = (int)(key[tid] & 0xffffffffu);
        g_srcidx[b * RR + tid] = s;
        mrg[s] = 1;
        int d = nidx[s];
        g_lnext[b * RR + tid] = atomicExch(&g_lhead[b * NSRC + d], tid);
    }
    __syncthreads();
    int um = mrg[tid] ? 0 : 1;
    scn[tid] = um; __syncthreads();
    for (int off = 1; off < 1024; off <<= 1) {
        int v = scn[tid];
        int v2 = (tid >= off) ? scn[tid - off] : 0;
        __syncthreads();
        scn[tid] = v + v2; __syncthreads();
    }
    int rnk = scn[tid] - um;
    if (um) { g_unmidx[b * RR + rnk] = tid; g_gather[b * NSRC + tid] = NDST + rnk; }
    else    { g_gather[b * NSRC + tid] = nidx[tid]; }
}

// ---------------- 4. fused merge build (emits tf32-rounded xm) ----------------
__global__ void buildall_k(const float* __restrict__ x) {
    int row = blockIdx.x;
    int b = row / MM, j = row - b * MM;
    int t = threadIdx.x;                    // 192
    float* dst = g_xm + (size_t)row * CC;
    if (j >= NDST) {
        int s = g_unmidx[b * RR + (j - NDST)];
        const float* src = x + ((size_t)b * NN + 2 * s) * CC;
        float4 v = *(const float4*)&src[t * 4];
        *(float4*)&dst[t * 4] =
            make_float4(tf32r(v.x), tf32r(v.y), tf32r(v.z), tf32r(v.w));
        return;
    }
    const float* dsrc = x + ((size_t)b * NN + 2 * j + 1) * CC;
    float4 v = *(const float4*)&dsrc[t * 4];
    float cntf = 1.f;
    int it = g_lhead[b * NSRC + j];
    while (it >= 0) {
        int s = g_srcidx[b * RR + it];
        float4 sv = *(const float4*)&x[((size_t)b * NN + 2 * s) * CC + t * 4];
        v.x += sv.x; v.y += sv.y; v.z += sv.z; v.w += sv.w;
        cntf += 1.f;
        it = g_lnext[b * RR + it];
    }
    float inv = 1.f / cntf;
    *(float4*)&dst[t * 4] =
        make_float4(tf32r(v.x * inv), tf32r(v.y * inv), tf32r(v.z * inv), tf32r(v.w * inv));
}

// ---------------- 5. tf32 GEMM (cp.async DB); rnd=1 -> tf32-round outputs ----------------
__global__ __launch_bounds__(256, 2) void gemm_tf32_k(
        const float* __restrict__ A, const float* __restrict__ Bm,
        const float* __restrict__ bias, float* __restrict__ Cm, int Nd, int Kd, int rnd) {
    __shared__ float As[2][128 * 20];
    __shared__ float Bs[2][128 * 20];
    int tid = threadIdx.x;
    int w = tid >> 5, l = tid & 31;
    int wm = w & 3, wn = w >> 2;
    int lr = l >> 2, lc = l & 3;
    int bm = blockIdx.y * 128, bn = blockIdx.x * 128;
    float acc[2][8][4] = {};

    int arow_a = (l & 7) + ((l >> 3) & 1) * 8;
    int acol_a = ((l >> 4) & 1) * 4;
    int arow_b = (l & 7) + ((l >> 4) & 1) * 8;
    int acol_b = ((l >> 3) & 1) * 4;
    unsigned aBase = smem_u32(As) + (unsigned)(((wm * 32 + arow_a) * 20 + acol_a) * 4);
    unsigned bBase = smem_u32(Bs) + (unsigned)(((wn * 64 + arow_b) * 20 + acol_b) * 4);

    int ar = tid >> 1, ak = (tid & 1) * 8;
    int bnn = tid & 127, bk = (tid >> 7) * 8;
    const float* Ap = A + (size_t)(bm + ar) * Kd + ak;
    const float* Bp = Bm + bn + bnn;
    unsigned adst = smem_u32(As) + (unsigned)((ar * 20 + ak) * 4);
    unsigned bdst = smem_u32(Bs) + (unsigned)((bnn * 20 + bk) * 4);

    auto issue = [&](int c, int buf) {
        unsigned off = buf * 10240u;
        const float* a = Ap + c * 16;
        cp16(adst + off, a);
        cp16(adst + off + 16, a + 4);
#pragma unroll
        for (int i = 0; i < 8; i++)
            cp4(bdst + off + i * 4, Bp + (size_t)(c * 16 + bk + i) * Nd);
    };

    int nchunk = Kd >> 4;
    issue(0, 0); cpcommit();
    int buf = 0;
    for (int c = 0; c < nchunk; c++) {
        cpwait0();
        __syncthreads();
        if (c + 1 < nchunk) { issue(c + 1, buf ^ 1); cpcommit(); }
        unsigned bo = (unsigned)(buf * 10240);
#pragma unroll
        for (int ks = 0; ks < 2; ks++) {
            unsigned a0[4], a1[4];
            ldsm4(a0, aBase + bo + ks * 32);
            ldsm4(a1, aBase + bo + 16 * 80 + ks * 32);
#pragma unroll
            for (int ntp = 0; ntp < 4; ntp++) {
                unsigned bq[4];
                ldsm4(bq, bBase + bo + ntp * 16 * 80 + ks * 32);
                mma8(acc[0][2 * ntp],     a0, bq);
                mma8(acc[1][2 * ntp],     a1, bq);
                mma8(acc[0][2 * ntp + 1], a0, bq + 2);
                mma8(acc[1][2 * ntp + 1], a1, bq + 2);
            }
        }
        buf ^= 1;
    }
#pragma unroll
    for (int mt = 0; mt < 2; mt++) {
        int r0 = bm + wm * 32 + mt * 16 + lr;
#pragma unroll
        for (int nt = 0; nt < 8; nt++) {
            int c = bn + wn * 64 + nt * 8 + 2 * lc;
            float b0 = bias[c], b1 = bias[c + 1];
            float o0 = acc[mt][nt][0] + b0, o1 = acc[mt][nt][1] + b1;
            float o2 = acc[mt][nt][2] + b0, o3 = acc[mt][nt][3] + b1;
            if (rnd) { o0 = tf32r(o0); o1 = tf32r(o1); o2 = tf32r(o2); o3 = tf32r(o3); }
            *(float2*)&Cm[(size_t)r0 * Nd + c] = make_float2(o0, o1);
            *(float2*)&Cm[(size_t)(r0 + 8) * Nd + c] = make_float2(o2, o3);
        }
    }
}

// ---------------- 6. flash attention: 1 sync/iter, K/V double-buffered, P in regs ----------------
__global__ __launch_bounds__(256, 2) void flash_tf32_k(
        const float* __restrict__ qkv, float* __restrict__ o) {
    extern __shared__ float sm[];
    float* Qs = sm;                     // [128][68]
    float* Ks = sm + 8704;              // [2][64][68]
    float* Vs = sm + 8704 + 8704;       // [2][64][68], V^T with slot-permuted cols

    int qt = blockIdx.x, bh = blockIdx.y;
    int b = bh / HH, h = bh % HH;
    const float* base = qkv + (size_t)b * MM * C3 + h * 64;
    int tid = threadIdx.x;
    int w = tid >> 5, l = tid & 31;
    int lr = l >> 2, lc = l & 3;
    int mr0 = w * 16 + lr;

    int arow_a = (l & 7) + ((l >> 3) & 1) * 8;
    int acol_a = ((l >> 4) & 1) * 4;
    int arow_b = (l & 7) + ((l >> 4) & 1) * 8;
    int acol_b = ((l >> 3) & 1) * 4;
    unsigned qB  = smem_u32(Qs) + (unsigned)(((w * 16 + arow_a) * 68 + acol_a) * 4);
    unsigned kB0 = smem_u32(Ks) + (unsigned)((arow_b * 68 + acol_b) * 4);
    unsigned vB0 = smem_u32(Vs) + (unsigned)((arow_b * 68 + acol_b) * 4);

    {   // Q fill: values pre-rounded tf32; *0.125 exact (power of 2)
        int r = tid >> 1, hf = (tid & 1) * 32;
        const float* qp = base + (size_t)(qt * 128 + r) * C3 + hf;
#pragma unroll
        for (int i = 0; i < 8; i++) {
            float4 v = *(const float4*)(qp + i * 4);
            *(float4*)&Qs[r * 68 + hf + i * 4] =
                make_float4(v.x * 0.125f, v.y * 0.125f, v.z * 0.125f, v.w * 0.125f);
        }
    }
    // K cp.async: thread handles row kr, 16 floats at kq
    int kr = tid >> 2, kq = (tid & 3) * 16;
    unsigned kdst = smem_u32(Ks) + (unsigned)((kr * 68 + kq) * 4);
    const float* kgp = base + CC + (size_t)kr * C3 + kq;
    // V staging: thread = column vd, rows vcb..vcb+15; store slot-permuted
    int vd = tid & 63, vcb = (tid >> 6) * 16;
    const float* vgp = base + 2 * CC + (size_t)vcb * C3 + vd;
    float vr[16];

    // prologue: V(0) -> regs; K(0) -> K[0] via cp.async
#pragma unroll
    for (int i = 0; i < 16; i++) vr[i] = vgp[(size_t)i * C3];
#pragma unroll
    for (int j = 0; j < 4; j++) cp16(kdst + j * 16, kgp + j * 4);
    cpcommit();

    float om[8][4] = {};
    float m0 = -INFINITY, m1 = -INFINITY, l0 = 0.f, l1 = 0.f;

    for (int kt = 0; kt < 24; kt++) {
        int buf = kt & 1;
        {   // STS V(kt) into V[buf], columns slot-permuted within 8-groups
            float* Vw = Vs + buf * 4352;
#pragma unroll
            for (int i = 0; i < 16; i++) {
                int c = vcb + i;
                int phys = (c & ~7) | (((c & 7) >> 1) + ((c & 1) << 2));
                Vw[vd * 68 + phys] = vr[i];
            }
        }
        cpwait0();          // K(kt) complete (only outstanding group)
        __syncthreads();    // K[buf], V[buf] visible; all warps past iter kt-1
        if (kt + 1 < 24) {  // issue K(kt+1) -> K[buf^1]
            unsigned d2 = kdst + (buf ^ 1) * 17408u;
            const float* g = kgp + (size_t)(kt + 1) * 64 * C3;
#pragma unroll
            for (int j = 0; j < 4; j++) cp16(d2 + j * 16, g + j * 4);
            cpcommit();
        }
        // S = Q K^T (Q pre-scaled)
        unsigned kB = kB0 + buf * 17408u;
        float s[8][4] = {};
#pragma unroll
        for (int ks = 0; ks < 8; ks++) {
            unsigned af[4];
            ldsm4(af, qB + ks * 32);
#pragma unroll
            for (int ntp = 0; ntp < 4; ntp++) {
                unsigned bq[4];
                ldsm4(bq, kB + ntp * 16 * 272 + ks * 32);
                mma8(s[2 * ntp],     af, bq);
                mma8(s[2 * ntp + 1], af, bq + 2);
            }
        }
        // prefetch V(kt+1) into regs (overlaps softmax + PV)
        if (kt + 1 < 24) {
            const float* g = vgp + (size_t)(kt + 1) * 64 * C3;
#pragma unroll
            for (int i = 0; i < 16; i++) vr[i] = g[(size_t)i * C3];
        }
        // online softmax; P stays in registers (tf32-rounded)
        float mx0 = -INFINITY, mx1 = -INFINITY;
#pragma unroll
        for (int nt = 0; nt < 8; nt++) {
            mx0 = fmaxf(mx0, fmaxf(s[nt][0], s[nt][1]));
            mx1 = fmaxf(mx1, fmaxf(s[nt][2], s[nt][3]));
        }
        mx0 = fmaxf(mx0, __shfl_xor_sync(0xffffffffu, mx0, 1));
        mx0 = fmaxf(mx0, __shfl_xor_sync(0xffffffffu, mx0, 2));
        mx1 = fmaxf(mx1, __shfl_xor_sync(0xffffffffu, mx1, 1));
        mx1 = fmaxf(mx1, __shfl_xor_sync(0xffffffffu, mx1, 2));
        float mn0 = fmaxf(m0, mx0), mn1 = fmaxf(m1, mx1);
        float al0 = __expf(m0 - mn0), al1 = __expf(m1 - mn1);
        m0 = mn0; m1 = mn1;
        float rs0 = 0.f, rs1 = 0.f;
#pragma unroll
        for (int nt = 0; nt < 8; nt++) {
            float p0 = __expf(s[nt][0] - mn0), p1 = __expf(s[nt][1] - mn0);
            float p2 = __expf(s[nt][2] - mn1), p3 = __expf(s[nt][3] - mn1);
            rs0 += p0 + p1; rs1 += p2 + p3;
            s[nt][0] = tf32r(p0); s[nt][1] = tf32r(p1);
            s[nt][2] = tf32r(p2); s[nt][3] = tf32r(p3);
        }
        rs0 += __shfl_xor_sync(0xffffffffu, rs0, 1);
        rs0 += __shfl_xor_sync(0xffffffffu, rs0, 2);
        rs1 += __shfl_xor_sync(0xffffffffu, rs1, 1);
        rs1 += __shfl_xor_sync(0xffffffffu, rs1, 2);
        l0 = l0 * al0 + rs0; l1 = l1 * al1 + rs1;
#pragma unroll
        for (int nt = 0; nt < 8; nt++) {
            om[nt][0] *= al0; om[nt][1] *= al0;
            om[nt][2] *= al1; om[nt][3] *= al1;
        }
        // O += P V : A-fragment = {p0, p2, p1, p3} (V cols slot-permuted to match)
        unsigned vB = vB0 + buf * 17408u;
#pragma unroll
        for (int ks = 0; ks < 8; ks++) {
            unsigned af[4] = { U(s[ks][0]), U(s[ks][2]), U(s[ks][1]), U(s[ks][3]) };
#pragma unroll
            for (int ntp = 0; ntp < 4; ntp++) {
                unsigned bq[4];
                ldsm4(bq, vB + ntp * 16 * 272 + ks * 32);
                mma8(om[2 * ntp],     af, bq);
                mma8(om[2 * ntp + 1], af, bq + 2);
            }
        }
    }
    float i0 = 1.f / l0, i1 = 1.f / l1;
    size_t row0 = (size_t)b * MM + qt * 128 + mr0;
#pragma unroll
    for (int nt = 0; nt < 8; nt++) {
        int c = h * 64 + nt * 8 + 2 * lc;
        *(float2*)&o[row0 * CC + c] =
            make_float2(tf32r(om[nt][0] * i0), tf32r(om[nt][1] * i0));
        *(float2*)&o[(row0 + 8) * CC + c] =
            make_float2(tf32r(om[nt][2] * i1), tf32r(om[nt][3] * i1));
    }
}

// ---------------- 7. unmerge ----------------
__global__ void unmerge_k(float* __restrict__ out) {
    int row = blockIdx.x;
    int b = row >> 11;
    int n = row & 2047;
    int yrow = (n & 1) ? (n >> 1) : g_gather[b * NSRC + (n >> 1)];
    const float* src = g_y + ((size_t)b * MM + yrow) * CC;
    float* dst = out + (size_t)row * CC;
    int t = threadIdx.x;                  // 192
    *(float4*)&dst[t * 4] = *(const float4*)&src[t * 4];
}

// ---------------- launcher ----------------
extern "C" void kernel_launch(void* const* d_in, const int* in_sizes, int n_in,
                              void* d_out, int out_size) {
    const float* x    = (const float*)d_in[0];
    const float* Wqkv = (const float*)d_in[1];
    const float* bqkv = (const float*)d_in[2];
    const float* Wo   = (const float*)d_in[3];
    const float* bo   = (const float*)d_in[4];
    float* out = (float*)d_out;

    float *xm, *qkvb, *attnb, *yb, *wq, *wo;
    cudaGetSymbolAddress((void**)&xm, g_xm);
    cudaGetSymbolAddress((void**)&qkvb, g_qkv);
    cudaGetSymbolAddress((void**)&attnb, g_attn);
    cudaGetSymbolAddress((void**)&yb, g_y);
    cudaGetSymbolAddress((void**)&wq, g_wqkv);
    cudaGetSymbolAddress((void**)&wo, g_wo);

    cudaFuncSetAttribute(flash_tf32_k, cudaFuncAttributeMaxDynamicSharedMemorySize, 104448);
    cudaFuncSetAttribute(match_mma_k, cudaFuncAttributeMaxDynamicSharedMemorySize, 81920);

    roundcp_k<<<(CC * C3 + 255) / 256, 256>>>(Wqkv, wq, CC * C3);
    roundcp_k<<<(CC * CC + 255) / 256, 256>>>(Wo, wo, CC * CC);
    metric_k<<<BB * NN, 256>>>(x);
    match_mma_k<<<dim3(8, 8, 8), 256, 81920>>>();
    topk_k<<<BB, 1024>>>();
    buildall_k<<<BB * MM, 192>>>(x);
    gemm_tf32_k<<<dim3(C3 / 128, (BB * MM) / 128), 256>>>(xm, wq, bqkv, qkvb, C3, CC, 1);
    flash_tf32_k<<<dim3(MM / 128, BB * HH), 256, 104448>>>(qkvb, attnb);
    gemm_tf32_k<<<dim3(CC / 128, (BB * MM) / 128), 256>>>(attnb, wo, bo, yb, CC, CC, 0);
    unmerge_k<<<BB * NN, 192>>>(out);
}